// round 14
// baseline (speedup 1.0000x reference)
#include <cuda_runtime.h>
#include <cuda_bf16.h>
#include <math.h>
#include <stdint.h>

#define Gn 1024
#define Hn 128
#define NNODES 100000
#define NEDGES 500000
#define EPS_LN 1e-5f
#define TILE 256
#define NT2 ((NEDGES + TILE - 1) / TILE)

// ---------------- device scratch ----------------
__device__ float g_u[Hn];
__device__ float g_vb[Hn];
__device__ uint4 g_Wsw[6144];          // 96KB bf16 W', [chunk][j][64k], XOR-16B swizzle
__device__ uint2 g_nbf[NNODES * 32];   // bf16 node tokens
__device__ uint2 g_qbf[Gn * 32];       // bf16 question tokens
__device__ float2 g_nstat[NNODES];     // per-row (sum, sumsq)
__device__ float2 g_qstat[Gn];
__device__ float g_logits[NEDGES];
__device__ float g_expsum[NNODES];
__device__ float g_lpg[Gn];
__device__ float g_selsum[Gn];

// smem byte offsets for k_edge (total 169984)
#define SM_PU    0
#define SM_PVB   512
#define SM_PW2   1024
#define SM_STAT  1536     // 256 x float2
#define SM_SPART 3584     // 512 x float
#define SM_WH    6144     // 96KB weights
#define SM_A0    104448   // 32KB A buf 0 (256 rows x 128B)
#define SM_A1    137216   // 32KB A buf 1
#define SM_TOTAL 169984

__device__ __forceinline__ uint32_t smem_u32(const void* p) {
    uint32_t a;
    asm("{ .reg .u64 t; cvta.to.shared.u64 t, %1; cvt.u32.u64 %0, t; }" : "=r"(a) : "l"(p));
    return a;
}
#define LDMX4(r, a) \
    asm volatile("ldmatrix.sync.aligned.m8n8.x4.shared.b16 {%0,%1,%2,%3}, [%4];" \
        : "=r"((r)[0]), "=r"((r)[1]), "=r"((r)[2]), "=r"((r)[3]) : "r"(a))
#define CP16(dst, src) \
    asm volatile("cp.async.cg.shared.global [%0], [%1], 16;" :: "r"(dst), "l"(src))
#define CP_COMMIT() asm volatile("cp.async.commit_group;" ::: "memory")
// warp-pair barrier: 64 threads (warps 2m, 2m+1), named barrier id = m+1
#define PAIRBAR(id) asm volatile("bar.sync %0, 64;" :: "r"(id) : "memory")

__device__ __forceinline__ void mma_bf16(float* d, const uint32_t* a, const uint32_t* b) {
    asm volatile("mma.sync.aligned.m16n8k16.row.col.f32.bf16.bf16.f32 "
        "{%0,%1,%2,%3}, {%4,%5,%6,%7}, {%8,%9}, {%0,%1,%2,%3};"
        : "+f"(d[0]), "+f"(d[1]), "+f"(d[2]), "+f"(d[3])
        : "r"(a[0]), "r"(a[1]), "r"(a[2]), "r"(a[3]), "r"(b[0]), "r"(b[1]));
}
__device__ __forceinline__ uint32_t cvt_bf16x2(float hi, float lo) {
    uint32_t r;
    asm("cvt.rn.bf16x2.f32 %0, %1, %2;" : "=r"(r) : "f"(hi), "f"(lo));
    return r;
}
__device__ __forceinline__ float geluf(float x) {
    return 0.5f * x * (1.0f + erff(x * 0.70710678118654752440f));
}

// ---------------- init ----------------
__global__ void k_init() {
    int i = blockIdx.x * blockDim.x + threadIdx.x;
    if (i < NNODES) g_expsum[i] = 0.0f;
    if (i < Gn) { g_lpg[i] = 0.0f; g_selsum[i] = 0.0f; }
}

// ---------------- convert fp32 tokens -> bf16 + per-row LN partial sums ----------------
__global__ void k_cvt(const float4* __restrict__ src, uint2* __restrict__ dst,
                      float2* __restrict__ stat, int nrows) {
    int wid = (blockIdx.x * blockDim.x + threadIdx.x) >> 5;
    int lane = threadIdx.x & 31;
    if (wid >= nrows) return;
    float4 v = src[(size_t)wid * 32 + lane];
    uint2 o;
    o.x = cvt_bf16x2(v.y, v.x);
    o.y = cvt_bf16x2(v.w, v.z);
    dst[(size_t)wid * 32 + lane] = o;
    float s = (v.x + v.y) + (v.z + v.w);
    float q = fmaf(v.x, v.x, fmaf(v.y, v.y, fmaf(v.z, v.z, v.w * v.w)));
    #pragma unroll
    for (int off = 16; off; off >>= 1) {
        s += __shfl_xor_sync(0xffffffffu, s, off);
        q += __shfl_xor_sync(0xffffffffu, q, off);
    }
    if (lane == 0) stat[wid] = make_float2(s, q);
}

// ---------------- prep: W' = g.*W -> bf16 swizzled; u, vb ----------------
__global__ void k_prep(const float* __restrict__ bw1, const float* __restrict__ blng,
                       const float* __restrict__ blnb, const float* __restrict__ bb1) {
    int j = blockIdx.x;     // output 0..127
    int k = threadIdx.x;    // 0..383
    __shared__ float rs[12], rv[12];
    float wraw = bw1[k * Hn + j];
    float wv = blng[k] * wraw;
    float vv = blnb[k] * wraw;
    int chunk = k >> 6, kloc = k & 63;
    uint32_t off = (uint32_t)(chunk * 16384 + j * 128 + ((kloc * 2) ^ ((j & 7) << 4)));
    *(unsigned short*)((char*)g_Wsw + off) = __bfloat16_as_ushort(__float2bfloat16(wv));
    float uu = wv;
    #pragma unroll
    for (int o = 16; o; o >>= 1) {
        uu += __shfl_xor_sync(0xffffffffu, uu, o);
        vv += __shfl_xor_sync(0xffffffffu, vv, o);
    }
    if ((k & 31) == 0) { rs[k >> 5] = uu; rv[k >> 5] = vv; }
    __syncthreads();
    if (k == 0) {
        float U = 0.f, V = 0.f;
        for (int i = 0; i < 12; i++) { U += rs[i]; V += rv[i]; }
        g_u[j] = U;
        g_vb[j] = V + bb1[j];
    }
}

// ---------------- fused start-attention + context MLP + log_z ----------------
__device__ __forceinline__ float bsum128(float v, float* red) {
    #pragma unroll
    for (int o = 16; o; o >>= 1) v += __shfl_xor_sync(0xffffffffu, v, o);
    __syncthreads();
    if ((threadIdx.x & 31) == 0) red[threadIdx.x >> 5] = v;
    __syncthreads();
    return red[0] + red[1] + red[2] + red[3];
}
__global__ void k_sctx(const float* __restrict__ nodes, const float* __restrict__ qt,
                       const int* __restrict__ locals, const int* __restrict__ ptr,
                       const float* __restrict__ cw1, const float* __restrict__ cb1,
                       const float* __restrict__ cw2, const float* __restrict__ cb2,
                       const float* __restrict__ ln1g, const float* __restrict__ ln1b,
                       const float* __restrict__ zw1, const float* __restrict__ zb1,
                       const float* __restrict__ zw2, const float* __restrict__ zb2,
                       float* __restrict__ out) {
    int g = blockIdx.x, t = threadIdx.x;  // 128 threads
    __shared__ float red[4];
    __shared__ float sc[64], salpha[64];
    __shared__ int   sidx[64];
    __shared__ float xin[256];
    __shared__ float h1[128];
    __shared__ float xh[128];
    int s0 = ptr[g], s1e = ptr[g + 1];
    int n = s1e - s0; if (n > 64) n = 64; if (n < 0) n = 0;
    float qv = qt[g * Hn + t];
    for (int s = 0; s < n; s++) {
        int nd = locals[s0 + s];
        if (t == 0) sidx[s] = nd;
        float p = nodes[nd * Hn + t] * qv;
        #pragma unroll
        for (int o = 16; o; o >>= 1) p += __shfl_xor_sync(0xffffffffu, p, o);
        if ((t & 31) == 0) red[t >> 5] = p;
        __syncthreads();
        if (t == 0) sc[s] = (red[0] + red[1] + red[2] + red[3]) * 0.08838834764831843f;
        __syncthreads();
    }
    if (t == 0) {
        float m = -INFINITY;
        for (int s = 0; s < n; s++) m = fmaxf(m, sc[s]);
        float d = 0.0f;
        for (int s = 0; s < n; s++) { float e = expf(sc[s] - m); salpha[s] = e; d += e; }
        float inv = 1.0f / d;
        for (int s = 0; s < n; s++) salpha[s] *= inv;
    }
    __syncthreads();
    float acc = 0.0f;
    for (int s = 0; s < n; s++) acc += salpha[s] * nodes[sidx[s] * Hn + t];
    xin[t] = acc;
    xin[128 + t] = qv;
    __syncthreads();
    float a0 = 0.f, a1 = 0.f, a2 = 0.f, a3 = 0.f;
    #pragma unroll 8
    for (int k = 0; k < 256; k += 4) {
        a0 = fmaf(xin[k + 0], cw1[(k + 0) * Hn + t], a0);
        a1 = fmaf(xin[k + 1], cw1[(k + 1) * Hn + t], a1);
        a2 = fmaf(xin[k + 2], cw1[(k + 2) * Hn + t], a2);
        a3 = fmaf(xin[k + 3], cw1[(k + 3) * Hn + t], a3);
    }
    h1[t] = geluf(cb1[t] + (a0 + a1) + (a2 + a3));
    __syncthreads();
    a0 = 0.f; a1 = 0.f; a2 = 0.f; a3 = 0.f;
    #pragma unroll 8
    for (int k = 0; k < 128; k += 4) {
        a0 = fmaf(h1[k + 0], cw2[(k + 0) * Hn + t], a0);
        a1 = fmaf(h1[k + 1], cw2[(k + 1) * Hn + t], a1);
        a2 = fmaf(h1[k + 2], cw2[(k + 2) * Hn + t], a2);
        a3 = fmaf(h1[k + 3], cw2[(k + 3) * Hn + t], a3);
    }
    float c = cb2[t] + (a0 + a1) + (a2 + a3);
    float mean = bsum128(c, red) * (1.0f / 128.0f);
    float d = c - mean;
    float var = bsum128(d * d, red) * (1.0f / 128.0f);
    xh[t] = d * rsqrtf(var + EPS_LN) * ln1g[t] + ln1b[t];
    __syncthreads();
    a0 = 0.f; a1 = 0.f; a2 = 0.f; a3 = 0.f;
    #pragma unroll 8
    for (int k = 0; k < 128; k += 4) {
        a0 = fmaf(xh[k + 0], zw1[(k + 0) * Hn + t], a0);
        a1 = fmaf(xh[k + 1], zw1[(k + 1) * Hn + t], a1);
        a2 = fmaf(xh[k + 2], zw1[(k + 2) * Hn + t], a2);
        a3 = fmaf(xh[k + 3], zw1[(k + 3) * Hn + t], a3);
    }
    float p = geluf(zb1[t] + (a0 + a1) + (a2 + a3)) * zw2[t];
    float lz = bsum128(p, red);
    if (t == 0) out[g * 3 + 0] = lz + zb2[0];
}

// ---------------- edge logits: bf16 GEMM; fully pair-decoupled tile loop ----------------
__global__ void __launch_bounds__(512, 1)
k_edge(const float* __restrict__ et,
       const int* __restrict__ ebatch, const int* __restrict__ eidx,
       const float* __restrict__ bw2, const float* __restrict__ bb2) {
    extern __shared__ char smem[];
    uint32_t sb = smem_u32(smem);
    int t = threadIdx.x, lane = t & 31;
    int w = t >> 5;
    int warp_m = w >> 1, warp_n = w & 1;
    int pb = warp_m + 1;            // named barrier id for this warp pair (1..8)

    // stage weights + params
    {
        uint4* dh = (uint4*)(smem + SM_WH);
        for (int i = t; i < 6144; i += 512) dh[i] = g_Wsw[i];
    }
    float* pu  = (float*)(smem + SM_PU);
    float* pvb = (float*)(smem + SM_PVB);
    float* pw2 = (float*)(smem + SM_PW2);
    float2* st = (float2*)(smem + SM_STAT);
    float* spart = (float*)(smem + SM_SPART);
    if (t < 128) { pu[t] = g_u[t]; pvb[t] = g_vb[t]; pw2[t] = bw2[t]; }
    __syncthreads();   // only block barrier: weights/params staged
    float bias2 = bb2[0];

    int r = t >> 1;                 // my row (0..255), 2 threads per row
    int hh = t & 1;                 // which half of the 64-float chunk
    uint32_t swrow = (uint32_t)((r & 7) << 4);
    uint32_t dst0 = sb + SM_A0 + r * 128;
    uint32_t dst1 = sb + SM_A1 + r * 128;

    for (int tile = blockIdx.x; tile < NT2; tile += gridDim.x) {
        int e0 = tile * TILE;
        int e = e0 + r; if (e >= NEDGES) e = NEDGES - 1;
        int br = ebatch[e], tgr = eidx[NEDGES + e];
        const char* srcQ = (const char*)(g_qbf + (size_t)br * 32);
        const char* srcN = (const char*)(g_nbf + (size_t)tgr * 32);

        // ---- edge tokens: fp32 LDG -> cvt -> STS (chunks 0,1), stats in-flight ----
        const float4* srcE = (const float4*)(et + (size_t)e * Hn) + hh * 8;
        float eS = 0.0f, eQ = 0.0f;
        #pragma unroll
        for (int c01 = 0; c01 < 2; c01++) {
            float4 fv[8];
            #pragma unroll
            for (int i = 0; i < 8; i++) fv[i] = srcE[c01 * 16 + i];
            uint32_t dst = c01 ? dst1 : dst0;
            #pragma unroll
            for (int i = 0; i < 8; i++) {
                float4 v = fv[i];
                eS += (v.x + v.y) + (v.z + v.w);
                eQ += fmaf(v.x, v.x, fmaf(v.y, v.y, fmaf(v.z, v.z, v.w * v.w)));
                uint2 H;
                H.x = cvt_bf16x2(v.y, v.x);
                H.y = cvt_bf16x2(v.w, v.z);
                uint32_t off = (uint32_t)((hh * 64 + i * 8) ^ swrow);
                *(uint2*)(smem + (dst - sb) + off) = H;
            }
        }
        // row LN stats: edge part (2-thread reduce) + node/question tables
        eS += __shfl_xor_sync(0xffffffffu, eS, 1);
        eQ += __shfl_xor_sync(0xffffffffu, eQ, 1);
        if (hh == 0) {
            float2 bq = g_qstat[br];
            float2 cn = g_nstat[tgr];
            st[r] = make_float2(eS + bq.x + cn.x, eQ + bq.y + cn.y);
        }

        float acc[2][8][4];
        #pragma unroll
        for (int a = 0; a < 2; a++)
            #pragma unroll
            for (int b = 0; b < 8; b++)
                #pragma unroll
                for (int d = 0; d < 4; d++) acc[a][b][d] = 0.0f;

        // ---- pipeline: pair-local sync; MMA c, then cp.async c+2 ----
        #pragma unroll 1
        for (int c = 0; c < 6; c++) {
            if (c >= 2) {
                if (c < 5) asm volatile("cp.async.wait_group 1;" ::: "memory");
                else       asm volatile("cp.async.wait_group 0;" ::: "memory");
            }
            PAIRBAR(pb);   // A rows [32*warp_m, +32) produced by this pair only
            uint32_t whc = sb + SM_WH + c * 16384;
            uint32_t abb = sb + ((c & 1) ? SM_A1 : SM_A0);
            #pragma unroll
            for (int ks = 0; ks < 4; ks++) {
                uint32_t ah[2][4], bh[16];
                #pragma unroll
                for (int mt = 0; mt < 2; mt++) {
                    int row = warp_m * 32 + mt * 16 + (lane & 7) + ((lane >> 3) & 1) * 8;
                    int colb = ks * 32 + (lane >> 4) * 16;
                    LDMX4(ah[mt], abb + (uint32_t)(row * 128 + (colb ^ ((row & 7) << 4))));
                }
                #pragma unroll
                for (int bt = 0; bt < 4; bt++) {
                    int j = warp_n * 64 + bt * 16 + (lane & 7) + (lane >> 4) * 8;
                    int kb = ks * 32 + ((lane >> 3) & 1) * 16;
                    LDMX4(&bh[bt * 4], whc + (uint32_t)(j * 128 + (kb ^ ((j & 7) << 4))));
                }
                #pragma unroll
                for (int mt = 0; mt < 2; mt++)
                    #pragma unroll
                    for (int nt = 0; nt < 8; nt++)
                        mma_bf16(acc[mt][nt], ah[mt], &bh[(nt >> 1) * 4 + (nt & 1) * 2]);
            }
            PAIRBAR(pb);   // pair done reading buf (c&1) before refilling it
            if (c < 4) {
                int cn = c + 2;
                int part = cn >> 1, half = cn & 1;
                const char* srcp = (part == 1) ? srcQ : srcN;
                uint32_t dst = (cn & 1) ? dst1 : dst0;
                #pragma unroll
                for (int i = 0; i < 4; i++) {
                    int sg = hh * 4 + i;
                    CP16(dst + ((sg * 16) ^ swrow), srcp + half * 128 + sg * 16);
                }
                CP_COMMIT();
            }
        }

        // epilogue: folded LN + GELU + dot(w2); pair-local writeback
        int gq = lane >> 2, cpair = (lane & 3) * 2;
        #pragma unroll
        for (int mt = 0; mt < 2; mt++) {
            #pragma unroll
            for (int half = 0; half < 2; half++) {
                int row = warp_m * 32 + mt * 16 + half * 8 + gq;
                float2 sv = st[row];
                float m = sv.x * (1.0f / 384.0f);
                float var = sv.y * (1.0f / 384.0f) - m * m;
                float is = rsqrtf(fmaxf(var, 0.0f) + EPS_LN);
                float pv = 0.0f;
                #pragma unroll
                for (int nt = 0; nt < 8; nt++) {
                    int j0 = warp_n * 64 + nt * 8 + cpair;
                    float d0 = acc[mt][nt][half * 2 + 0];
                    float d1 = acc[mt][nt][half * 2 + 1];
                    float y0 = (d0 - m * pu[j0])     * is + pvb[j0];
                    float y1 = (d1 - m * pu[j0 + 1]) * is + pvb[j0 + 1];
                    pv = fmaf(geluf(y0), pw2[j0], pv);
                    pv = fmaf(geluf(y1), pw2[j0 + 1], pv);
                }
                pv += __shfl_xor_sync(0xffffffffu, pv, 1);
                pv += __shfl_xor_sync(0xffffffffu, pv, 2);
                if ((lane & 3) == 0) spart[warp_n * 256 + row] = pv;
            }
        }
        PAIRBAR(pb);   // both warps' spart partials for this pair's 32 rows ready
        if (warp_n == 0) {
            int row = warp_m * 32 + lane;
            int e2 = e0 + row;
            if (e2 < NEDGES) {
                float L = spart[row] + spart[256 + row] + bias2;
                g_logits[e2] = L;
                atomicAdd(&g_expsum[eidx[NEDGES + e2]], expf(L));
            }
        }
        PAIRBAR(pb);   // spart/st/A-rows safe to reuse next tile
    }
}

// ---------------- per-graph selected log-prob sums ----------------
__global__ void k_lpb(const int* __restrict__ eidx, const int* __restrict__ ebatch,
                      const int* __restrict__ mask) {
    const int CH = 16;
    int base = (blockIdx.x * blockDim.x + threadIdx.x) * CH;
    if (base >= NEDGES) return;
    int end = base + CH; if (end > NEDGES) end = NEDGES;
    int cur = -1; float aL = 0.0f, aS = 0.0f;
    for (int e = base; e < end; e++) {
        int b = ebatch[e];
        if (b != cur) {
            if (cur >= 0 && (aL != 0.0f || aS != 0.0f)) {
                atomicAdd(&g_lpg[cur], aL);
                atomicAdd(&g_selsum[cur], aS);
            }
            cur = b; aL = 0.0f; aS = 0.0f;
        }
        if (mask[e] != 0) {
            int tg = eidx[NEDGES + e];
            float lp = g_logits[e] - logf(g_expsum[tg]);
            aL += lp; aS += 1.0f;
        }
    }
    if (cur >= 0 && (aL != 0.0f || aS != 0.0f)) {
        atomicAdd(&g_lpg[cur], aL);
        atomicAdd(&g_selsum[cur], aS);
    }
}
__global__ void k_fin(float* __restrict__ out) {
    int g = threadIdx.x;
    __shared__ float rs[32], rc[32];
    __shared__ float s_res;
    float lpg = g_lpg[g];
    float has = (g_selsum[g] > 0.0f) ? 1.0f : 0.0f;
    float v1 = -lpg * has, v2 = has;
    #pragma unroll
    for (int o = 16; o; o >>= 1) {
        v1 += __shfl_xor_sync(0xffffffffu, v1, o);
        v2 += __shfl_xor_sync(0xffffffffu, v2, o);
    }
    if ((g & 31) == 0) { rs[g >> 5] = v1; rc[g >> 5] = v2; }
    __syncthreads();
    if (g < 32) {
        float a = rs[g], b = rc[g];
        #pragma unroll
        for (int o = 16; o; o >>= 1) {
            a += __shfl_xor_sync(0xffffffffu, a, o);
            b += __shfl_xor_sync(0xffffffffu, b, o);
        }
        if (g == 0) s_res = a / fmaxf(b, 1.0f);
    }
    __syncthreads();
    out[g * 3 + 1] = lpg;
    out[g * 3 + 2] = s_res;
}

// ---------------- host ----------------
extern "C" void kernel_launch(void* const* d_in, const int* in_sizes, int n_in,
                              void* d_out, int out_size) {
    int I_node, I_q, I_edge, I_loc, I_ptr, I_eb, I_mask, I_eidx;
    int I_ln1g, I_ln1b, I_zw1, I_zb1, I_zw2, I_zb2;
    int I_cw1, I_cb1, I_cw2, I_cb2, I_blng, I_blnb, I_bw1, I_bb1, I_bw2, I_bb2;
    if (in_sizes[3] == 4096) {  // dict order
        I_node = 0; I_q = 1; I_edge = 2; I_loc = 3; I_ptr = 4; I_eb = 5; I_mask = 6; I_eidx = 7;
        I_ln1g = 8; I_ln1b = 9; I_zw1 = 10; I_zb1 = 11; I_zw2 = 12; I_zb2 = 13;
        I_cw1 = 14; I_cb1 = 15; I_cw2 = 16; I_cb2 = 17;
        I_blng = 18; I_blnb = 19; I_bw1 = 20; I_bb1 = 21; I_bw2 = 22; I_bb2 = 23;
    } else {                    // signature order
        I_node = 0; I_q = 1; I_edge = 2;
        I_ln1g = 3; I_ln1b = 4; I_zw1 = 5; I_zb1 = 6; I_zw2 = 7; I_zb2 = 8;
        I_cw1 = 9; I_cb1 = 10; I_cw2 = 11; I_cb2 = 12;
        I_blng = 13; I_blnb = 14; I_bw1 = 15; I_bb1 = 16; I_bw2 = 17; I_bb2 = 18;
        I_loc = 19; I_ptr = 20; I_eb = 21; I_mask = 22; I_eidx = 23;
    }

    const float* nodes = (const float*)d_in[I_node];
    const float* qt    = (const float*)d_in[I_q];
    const float* et    = (const float*)d_in[I_edge];
    const int*   locs  = (const int*)d_in[I_loc];
    const int*   ptr   = (const int*)d_in[I_ptr];
    const int*   ebat  = (const int*)d_in[I_eb];
    const int*   mask  = (const int*)d_in[I_mask];
    const int*   eidx  = (const int*)d_in[I_eidx];
    float* out = (float*)d_out;

    int dev = 0, nsm = 148;
    cudaGetDevice(&dev);
    cudaDeviceGetAttribute(&nsm, cudaDevAttrMultiProcessorCount, dev);

    static int smem_set = 0;
    if (!smem_set) {
        cudaFuncSetAttribute(k_edge, cudaFuncAttributeMaxDynamicSharedMemorySize, SM_TOTAL);
        smem_set = 1;
    }

    uint2* p_nbf; uint2* p_qbf;
    float2* p_nst; float2* p_qst;
    cudaGetSymbolAddress((void**)&p_nbf, g_nbf);
    cudaGetSymbolAddress((void**)&p_qbf, g_qbf);
    cudaGetSymbolAddress((void**)&p_nst, g_nstat);
    cudaGetSymbolAddress((void**)&p_qst, g_qstat);

    k_init<<<(NNODES + 255) / 256, 256>>>();
    k_prep<<<128, 384>>>((const float*)d_in[I_bw1], (const float*)d_in[I_blng],
                         (const float*)d_in[I_blnb], (const float*)d_in[I_bb1]);
    k_cvt<<<(NNODES + 7) / 8, 256>>>((const float4*)nodes, p_nbf, p_nst, NNODES);
    k_cvt<<<(Gn + 7) / 8, 256>>>((const float4*)qt, p_qbf, p_qst, Gn);
    k_sctx<<<Gn, 128>>>(nodes, qt, locs, ptr,
                        (const float*)d_in[I_cw1], (const float*)d_in[I_cb1],
                        (const float*)d_in[I_cw2], (const float*)d_in[I_cb2],
                        (const float*)d_in[I_ln1g], (const float*)d_in[I_ln1b],
                        (const float*)d_in[I_zw1], (const float*)d_in[I_zb1],
                        (const float*)d_in[I_zw2], (const float*)d_in[I_zb2],
                        out);
    k_edge<<<nsm, 512, SM_TOTAL>>>(et, ebat, eidx,
                                   (const float*)d_in[I_bw2], (const float*)d_in[I_bb2]);
    k_lpb<<<((NEDGES + 15) / 16 + 255) / 256, 256>>>(eidx, ebat, mask);
    k_fin<<<1, 1024>>>(out);
}

// round 15
// speedup vs baseline: 1.1950x; 1.1950x over previous
#include <cuda_runtime.h>
#include <cuda_bf16.h>
#include <math.h>
#include <stdint.h>

#define Gn 1024
#define Hn 128
#define NNODES 100000
#define NEDGES 500000
#define EPS_LN 1e-5f
#define TILE 256
#define NT2 ((NEDGES + TILE - 1) / TILE)

// ---------------- device scratch ----------------
__device__ float g_summary[Gn * Hn];
__device__ float g_u[Hn];
__device__ float g_vb[Hn];
__device__ uint4 g_Wsw[6144];          // 96KB bf16 W', [chunk][j][64k], XOR-16B swizzle
__device__ uint2 g_nbf[NNODES * 32];   // bf16 node tokens
__device__ uint2 g_qbf[Gn * 32];       // bf16 question tokens
__device__ float2 g_nstat[NNODES];     // per-row (sum, sumsq)
__device__ float2 g_qstat[Gn];
__device__ float g_logits[NEDGES];
__device__ float g_expsum[NNODES];
__device__ float g_lpg[Gn];
__device__ float g_selsum[Gn];

// smem byte offsets for k_edge (total 169984)
#define SM_PU    0
#define SM_PVB   512
#define SM_PW2   1024
#define SM_STAT  1536     // 256 x float2
#define SM_SPART 3584     // 512 x float
#define SM_WH    6144     // 96KB weights
#define SM_A0    104448   // 32KB A buf 0 (256 rows x 128B)
#define SM_A1    137216   // 32KB A buf 1
#define SM_TOTAL 169984

__device__ __forceinline__ uint32_t smem_u32(const void* p) {
    uint32_t a;
    asm("{ .reg .u64 t; cvta.to.shared.u64 t, %1; cvt.u32.u64 %0, t; }" : "=r"(a) : "l"(p));
    return a;
}
#define LDMX4(r, a) \
    asm volatile("ldmatrix.sync.aligned.m8n8.x4.shared.b16 {%0,%1,%2,%3}, [%4];" \
        : "=r"((r)[0]), "=r"((r)[1]), "=r"((r)[2]), "=r"((r)[3]) : "r"(a))
#define CP16(dst, src) \
    asm volatile("cp.async.cg.shared.global [%0], [%1], 16;" :: "r"(dst), "l"(src))
#define CP_COMMIT() asm volatile("cp.async.commit_group;" ::: "memory")
// warp-pair barrier: 64 threads (warps 2m, 2m+1), named barrier id = m+1
#define PAIRBAR(id) asm volatile("bar.sync %0, 64;" :: "r"(id) : "memory")

__device__ __forceinline__ void mma_bf16(float* d, const uint32_t* a, const uint32_t* b) {
    asm volatile("mma.sync.aligned.m16n8k16.row.col.f32.bf16.bf16.f32 "
        "{%0,%1,%2,%3}, {%4,%5,%6,%7}, {%8,%9}, {%0,%1,%2,%3};"
        : "+f"(d[0]), "+f"(d[1]), "+f"(d[2]), "+f"(d[3])
        : "r"(a[0]), "r"(a[1]), "r"(a[2]), "r"(a[3]), "r"(b[0]), "r"(b[1]));
}
__device__ __forceinline__ uint32_t cvt_bf16x2(float hi, float lo) {
    uint32_t r;
    asm("cvt.rn.bf16x2.f32 %0, %1, %2;" : "=r"(r) : "f"(hi), "f"(lo));
    return r;
}
__device__ __forceinline__ float geluf(float x) {
    return 0.5f * x * (1.0f + erff(x * 0.70710678118654752440f));
}

// ---------------- init ----------------
__global__ void k_init() {
    int i = blockIdx.x * blockDim.x + threadIdx.x;
    if (i < NNODES) g_expsum[i] = 0.0f;
    if (i < Gn) { g_lpg[i] = 0.0f; g_selsum[i] = 0.0f; }
}

// ---------------- convert fp32 tokens -> bf16 + per-row LN partial sums ----------------
__global__ void k_cvt(const float4* __restrict__ src, uint2* __restrict__ dst,
                      float2* __restrict__ stat, int nrows) {
    int wid = (blockIdx.x * blockDim.x + threadIdx.x) >> 5;
    int lane = threadIdx.x & 31;
    if (wid >= nrows) return;
    float4 v = src[(size_t)wid * 32 + lane];
    uint2 o;
    o.x = cvt_bf16x2(v.y, v.x);
    o.y = cvt_bf16x2(v.w, v.z);
    dst[(size_t)wid * 32 + lane] = o;
    float s = (v.x + v.y) + (v.z + v.w);
    float q = fmaf(v.x, v.x, fmaf(v.y, v.y, fmaf(v.z, v.z, v.w * v.w)));
    #pragma unroll
    for (int off = 16; off; off >>= 1) {
        s += __shfl_xor_sync(0xffffffffu, s, off);
        q += __shfl_xor_sync(0xffffffffu, q, off);
    }
    if (lane == 0) stat[wid] = make_float2(s, q);
}

// ---------------- prep: W' = g.*W -> bf16 swizzled; u, vb ----------------
__global__ void k_prep(const float* __restrict__ bw1, const float* __restrict__ blng,
                       const float* __restrict__ blnb, const float* __restrict__ bb1) {
    int j = blockIdx.x;     // output 0..127
    int k = threadIdx.x;    // 0..383
    __shared__ float rs[12], rv[12];
    float wraw = bw1[k * Hn + j];
    float wv = blng[k] * wraw;
    float vv = blnb[k] * wraw;
    int chunk = k >> 6, kloc = k & 63;
    uint32_t off = (uint32_t)(chunk * 16384 + j * 128 + ((kloc * 2) ^ ((j & 7) << 4)));
    *(unsigned short*)((char*)g_Wsw + off) = __bfloat16_as_ushort(__float2bfloat16(wv));
    float uu = wv;
    #pragma unroll
    for (int o = 16; o; o >>= 1) {
        uu += __shfl_xor_sync(0xffffffffu, uu, o);
        vv += __shfl_xor_sync(0xffffffffu, vv, o);
    }
    if ((k & 31) == 0) { rs[k >> 5] = uu; rv[k >> 5] = vv; }
    __syncthreads();
    if (k == 0) {
        float U = 0.f, V = 0.f;
        for (int i = 0; i < 12; i++) { U += rs[i]; V += rv[i]; }
        g_u[j] = U;
        g_vb[j] = V + bb1[j];
    }
}

// ---------------- start-node attention -> summary (fully parallel, 1024 blocks) ----------------
__global__ void k_start(const float* __restrict__ nodes, const float* __restrict__ qt,
                        const int* __restrict__ locals, const int* __restrict__ ptr) {
    int g = blockIdx.x, t = threadIdx.x;
    __shared__ float red[4];
    __shared__ float sc[64], salpha[64];
    __shared__ int   sidx[64];
    int s0 = ptr[g], s1e = ptr[g + 1];
    int n = s1e - s0; if (n > 64) n = 64; if (n < 0) n = 0;
    float qv = qt[g * Hn + t];
    for (int s = 0; s < n; s++) {
        int nd = locals[s0 + s];
        if (t == 0) sidx[s] = nd;
        float p = nodes[nd * Hn + t] * qv;
        #pragma unroll
        for (int o = 16; o; o >>= 1) p += __shfl_xor_sync(0xffffffffu, p, o);
        if ((t & 31) == 0) red[t >> 5] = p;
        __syncthreads();
        if (t == 0) sc[s] = (red[0] + red[1] + red[2] + red[3]) * 0.08838834764831843f;
        __syncthreads();
    }
    if (t == 0) {
        float m = -INFINITY;
        for (int s = 0; s < n; s++) m = fmaxf(m, sc[s]);
        float d = 0.0f;
        for (int s = 0; s < n; s++) { float e = expf(sc[s] - m); salpha[s] = e; d += e; }
        float inv = 1.0f / d;
        for (int s = 0; s < n; s++) salpha[s] *= inv;
    }
    __syncthreads();
    float acc = 0.0f;
    for (int s = 0; s < n; s++) acc += salpha[s] * nodes[sidx[s] * Hn + t];
    g_summary[g * Hn + t] = acc;
}

// ---------------- context MLP + log_z head: 4 graphs/block, weight reuse ----------------
__device__ __forceinline__ float bsum128(float v, float* red) {
    #pragma unroll
    for (int o = 16; o; o >>= 1) v += __shfl_xor_sync(0xffffffffu, v, o);
    __syncthreads();
    if ((threadIdx.x & 31) == 0) red[threadIdx.x >> 5] = v;
    __syncthreads();
    return red[0] + red[1] + red[2] + red[3];
}
__global__ void k_ctx4(const float* __restrict__ qt,
                       const float* __restrict__ cw1, const float* __restrict__ cb1,
                       const float* __restrict__ cw2, const float* __restrict__ cb2,
                       const float* __restrict__ ln1g, const float* __restrict__ ln1b,
                       const float* __restrict__ zw1, const float* __restrict__ zb1,
                       const float* __restrict__ zw2, const float* __restrict__ zb2,
                       float* __restrict__ out) {
    int t = threadIdx.x;  // 128 threads, 4 graphs per block
    __shared__ float red[4];
    __shared__ float xin[4][256];
    __shared__ float h1[4][128];
    __shared__ float xh[4][128];
    #pragma unroll
    for (int gi = 0; gi < 4; gi++) {
        int g = blockIdx.x * 4 + gi;
        xin[gi][t]       = g_summary[g * Hn + t];
        xin[gi][128 + t] = qt[g * Hn + t];
    }
    __syncthreads();
    // layer 1: one weight LDG feeds 4 graphs
    float a0 = 0.f, a1 = 0.f, a2 = 0.f, a3 = 0.f;
    #pragma unroll 4
    for (int k = 0; k < 256; k++) {
        float wv = cw1[k * Hn + t];
        a0 = fmaf(xin[0][k], wv, a0);
        a1 = fmaf(xin[1][k], wv, a1);
        a2 = fmaf(xin[2][k], wv, a2);
        a3 = fmaf(xin[3][k], wv, a3);
    }
    {
        float cb = cb1[t];
        h1[0][t] = geluf(cb + a0);
        h1[1][t] = geluf(cb + a1);
        h1[2][t] = geluf(cb + a2);
        h1[3][t] = geluf(cb + a3);
    }
    __syncthreads();
    // layer 2
    a0 = 0.f; a1 = 0.f; a2 = 0.f; a3 = 0.f;
    #pragma unroll 4
    for (int k = 0; k < 128; k++) {
        float wv = cw2[k * Hn + t];
        a0 = fmaf(h1[0][k], wv, a0);
        a1 = fmaf(h1[1][k], wv, a1);
        a2 = fmaf(h1[2][k], wv, a2);
        a3 = fmaf(h1[3][k], wv, a3);
    }
    {
        float cb = cb2[t], lg = ln1g[t], lb = ln1b[t];
        float cg[4] = { cb + a0, cb + a1, cb + a2, cb + a3 };
        #pragma unroll 1
        for (int gi = 0; gi < 4; gi++) {
            float mean = bsum128(cg[gi], red) * (1.0f / 128.0f);
            float d = cg[gi] - mean;
            float var = bsum128(d * d, red) * (1.0f / 128.0f);
            xh[gi][t] = d * rsqrtf(var + EPS_LN) * lg + lb;
        }
    }
    __syncthreads();
    // z head
    a0 = 0.f; a1 = 0.f; a2 = 0.f; a3 = 0.f;
    #pragma unroll 4
    for (int k = 0; k < 128; k++) {
        float wv = zw1[k * Hn + t];
        a0 = fmaf(xh[0][k], wv, a0);
        a1 = fmaf(xh[1][k], wv, a1);
        a2 = fmaf(xh[2][k], wv, a2);
        a3 = fmaf(xh[3][k], wv, a3);
    }
    {
        float zb = zb1[t], zw = zw2[t], zb2v = zb2[0];
        float pg[4] = { geluf(zb + a0) * zw, geluf(zb + a1) * zw,
                        geluf(zb + a2) * zw, geluf(zb + a3) * zw };
        #pragma unroll 1
        for (int gi = 0; gi < 4; gi++) {
            float lz = bsum128(pg[gi], red);
            if (t == 0) out[(blockIdx.x * 4 + gi) * 3 + 0] = lz + zb2v;
        }
    }
}

// ---------------- edge logits: bf16 GEMM (R13 structure, frozen) ----------------
__global__ void __launch_bounds__(512, 1)
k_edge(const float* __restrict__ et,
       const int* __restrict__ ebatch, const int* __restrict__ eidx,
       const float* __restrict__ bw2, const float* __restrict__ bb2) {
    extern __shared__ char smem[];
    uint32_t sb = smem_u32(smem);
    int t = threadIdx.x, lane = t & 31;
    int w = t >> 5;
    int warp_m = w >> 1, warp_n = w & 1;
    int pb = warp_m + 1;            // named barrier id for this warp pair (1..8)

    // stage weights + params
    {
        uint4* dh = (uint4*)(smem + SM_WH);
        for (int i = t; i < 6144; i += 512) dh[i] = g_Wsw[i];
    }
    float* pu  = (float*)(smem + SM_PU);
    float* pvb = (float*)(smem + SM_PVB);
    float* pw2 = (float*)(smem + SM_PW2);
    float2* st = (float2*)(smem + SM_STAT);
    float* spart = (float*)(smem + SM_SPART);
    if (t < 128) { pu[t] = g_u[t]; pvb[t] = g_vb[t]; pw2[t] = bw2[t]; }
    __syncthreads();
    float bias2 = bb2[0];

    int r = t >> 1;                 // my row (0..255), 2 threads per row
    int hh = t & 1;                 // which half of the 64-float chunk
    uint32_t swrow = (uint32_t)((r & 7) << 4);
    uint32_t dst0 = sb + SM_A0 + r * 128;
    uint32_t dst1 = sb + SM_A1 + r * 128;

    for (int tile = blockIdx.x; tile < NT2; tile += gridDim.x) {
        int e0 = tile * TILE;
        int e = e0 + r; if (e >= NEDGES) e = NEDGES - 1;
        int br = ebatch[e], tgr = eidx[NEDGES + e];
        const char* srcQ = (const char*)(g_qbf + (size_t)br * 32);
        const char* srcN = (const char*)(g_nbf + (size_t)tgr * 32);

        // ---- edge tokens: fp32 LDG -> cvt -> STS (chunks 0,1), stats in-flight ----
        const float4* srcE = (const float4*)(et + (size_t)e * Hn) + hh * 8;
        float eS = 0.0f, eQ = 0.0f;
        #pragma unroll
        for (int c01 = 0; c01 < 2; c01++) {
            float4 fv[8];
            #pragma unroll
            for (int i = 0; i < 8; i++) fv[i] = srcE[c01 * 16 + i];
            uint32_t dst = c01 ? dst1 : dst0;
            #pragma unroll
            for (int i = 0; i < 8; i++) {
                float4 v = fv[i];
                eS += (v.x + v.y) + (v.z + v.w);
                eQ += fmaf(v.x, v.x, fmaf(v.y, v.y, fmaf(v.z, v.z, v.w * v.w)));
                uint2 H;
                H.x = cvt_bf16x2(v.y, v.x);
                H.y = cvt_bf16x2(v.w, v.z);
                uint32_t off = (uint32_t)((hh * 64 + i * 8) ^ swrow);
                *(uint2*)(smem + (dst - sb) + off) = H;
            }
        }
        // row LN stats: edge part (2-thread reduce) + node/question tables
        eS += __shfl_xor_sync(0xffffffffu, eS, 1);
        eQ += __shfl_xor_sync(0xffffffffu, eQ, 1);
        if (hh == 0) {
            float2 bq = g_qstat[br];
            float2 cn = g_nstat[tgr];
            st[r] = make_float2(eS + bq.x + cn.x, eQ + bq.y + cn.y);
        }

        float acc[2][8][4];
        #pragma unroll
        for (int a = 0; a < 2; a++)
            #pragma unroll
            for (int b = 0; b < 8; b++)
                #pragma unroll
                for (int d = 0; d < 4; d++) acc[a][b][d] = 0.0f;

        // ---- pipeline: pair-local sync; MMA c, then cp.async c+2 ----
        #pragma unroll 1
        for (int c = 0; c < 6; c++) {
            if (c >= 2) {
                if (c < 5) asm volatile("cp.async.wait_group 1;" ::: "memory");
                else       asm volatile("cp.async.wait_group 0;" ::: "memory");
            }
            PAIRBAR(pb);   // A rows [32*warp_m, +32) produced by this pair only
            uint32_t whc = sb + SM_WH + c * 16384;
            uint32_t abb = sb + ((c & 1) ? SM_A1 : SM_A0);
            #pragma unroll
            for (int ks = 0; ks < 4; ks++) {
                uint32_t ah[2][4], bh[16];
                #pragma unroll
                for (int mt = 0; mt < 2; mt++) {
                    int row = warp_m * 32 + mt * 16 + (lane & 7) + ((lane >> 3) & 1) * 8;
                    int colb = ks * 32 + (lane >> 4) * 16;
                    LDMX4(ah[mt], abb + (uint32_t)(row * 128 + (colb ^ ((row & 7) << 4))));
                }
                #pragma unroll
                for (int bt = 0; bt < 4; bt++) {
                    int j = warp_n * 64 + bt * 16 + (lane & 7) + (lane >> 4) * 8;
                    int kb = ks * 32 + ((lane >> 3) & 1) * 16;
                    LDMX4(&bh[bt * 4], whc + (uint32_t)(j * 128 + (kb ^ ((j & 7) << 4))));
                }
                #pragma unroll
                for (int mt = 0; mt < 2; mt++)
                    #pragma unroll
                    for (int nt = 0; nt < 8; nt++)
                        mma_bf16(acc[mt][nt], ah[mt], &bh[(nt >> 1) * 4 + (nt & 1) * 2]);
            }
            PAIRBAR(pb);   // pair done reading buf (c&1) before refilling it
            if (c < 4) {
                int cn = c + 2;
                int part = cn >> 1, half = cn & 1;
                const char* srcp = (part == 1) ? srcQ : srcN;
                uint32_t dst = (cn & 1) ? dst1 : dst0;
                #pragma unroll
                for (int i = 0; i < 4; i++) {
                    int sg = hh * 4 + i;
                    CP16(dst + ((sg * 16) ^ swrow), srcp + half * 128 + sg * 16);
                }
                CP_COMMIT();
            }
        }

        // epilogue: folded LN + GELU + dot(w2); fused node expsum atomic
        int gq = lane >> 2, cpair = (lane & 3) * 2;
        #pragma unroll
        for (int mt = 0; mt < 2; mt++) {
            #pragma unroll
            for (int half = 0; half < 2; half++) {
                int row = warp_m * 32 + mt * 16 + half * 8 + gq;
                float2 sv = st[row];
                float m = sv.x * (1.0f / 384.0f);
                float var = sv.y * (1.0f / 384.0f) - m * m;
                float is = rsqrtf(fmaxf(var, 0.0f) + EPS_LN);
                float pv = 0.0f;
                #pragma unroll
                for (int nt = 0; nt < 8; nt++) {
                    int j0 = warp_n * 64 + nt * 8 + cpair;
                    float d0 = acc[mt][nt][half * 2 + 0];
                    float d1 = acc[mt][nt][half * 2 + 1];
                    float y0 = (d0 - m * pu[j0])     * is + pvb[j0];
                    float y1 = (d1 - m * pu[j0 + 1]) * is + pvb[j0 + 1];
                    pv = fmaf(geluf(y0), pw2[j0], pv);
                    pv = fmaf(geluf(y1), pw2[j0 + 1], pv);
                }
                pv += __shfl_xor_sync(0xffffffffu, pv, 1);
                pv += __shfl_xor_sync(0xffffffffu, pv, 2);
                if ((lane & 3) == 0) spart[warp_n * 256 + row] = pv;
            }
        }
        __syncthreads();
        if (t < 256) {
            int e2 = e0 + t;
            if (e2 < NEDGES) {
                float L = spart[t] + spart[256 + t] + bias2;
                g_logits[e2] = L;
                atomicAdd(&g_expsum[eidx[NEDGES + e2]], expf(L));
            }
        }
        __syncthreads();
    }
}

// ---------------- per-graph selected log-prob sums ----------------
__global__ void k_lpb(const int* __restrict__ eidx, const int* __restrict__ ebatch,
                      const int* __restrict__ mask) {
    const int CH = 16;
    int base = (blockIdx.x * blockDim.x + threadIdx.x) * CH;
    if (base >= NEDGES) return;
    int end = base + CH; if (end > NEDGES) end = NEDGES;
    int cur = -1; float aL = 0.0f, aS = 0.0f;
    for (int e = base; e < end; e++) {
        int b = ebatch[e];
        if (b != cur) {
            if (cur >= 0 && (aL != 0.0f || aS != 0.0f)) {
                atomicAdd(&g_lpg[cur], aL);
                atomicAdd(&g_selsum[cur], aS);
            }
            cur = b; aL = 0.0f; aS = 0.0f;
        }
        if (mask[e] != 0) {
            int tg = eidx[NEDGES + e];
            float lp = g_logits[e] - logf(g_expsum[tg]);
            aL += lp; aS += 1.0f;
        }
    }
    if (cur >= 0 && (aL != 0.0f || aS != 0.0f)) {
        atomicAdd(&g_lpg[cur], aL);
        atomicAdd(&g_selsum[cur], aS);
    }
}
__global__ void k_fin(float* __restrict__ out) {
    int g = threadIdx.x;
    __shared__ float rs[32], rc[32];
    __shared__ float s_res;
    float lpg = g_lpg[g];
    float has = (g_selsum[g] > 0.0f) ? 1.0f : 0.0f;
    float v1 = -lpg * has, v2 = has;
    #pragma unroll
    for (int o = 16; o; o >>= 1) {
        v1 += __shfl_xor_sync(0xffffffffu, v1, o);
        v2 += __shfl_xor_sync(0xffffffffu, v2, o);
    }
    if ((g & 31) == 0) { rs[g >> 5] = v1; rc[g >> 5] = v2; }
    __syncthreads();
    if (g < 32) {
        float a = rs[g], b = rc[g];
        #pragma unroll
        for (int o = 16; o; o >>= 1) {
            a += __shfl_xor_sync(0xffffffffu, a, o);
            b += __shfl_xor_sync(0xffffffffu, b, o);
        }
        if (g == 0) s_res = a / fmaxf(b, 1.0f);
    }
    __syncthreads();
    out[g * 3 + 1] = lpg;
    out[g * 3 + 2] = s_res;
}

// ---------------- host ----------------
extern "C" void kernel_launch(void* const* d_in, const int* in_sizes, int n_in,
                              void* d_out, int out_size) {
    int I_node, I_q, I_edge, I_loc, I_ptr, I_eb, I_mask, I_eidx;
    int I_ln1g, I_ln1b, I_zw1, I_zb1, I_zw2, I_zb2;
    int I_cw1, I_cb1, I_cw2, I_cb2, I_blng, I_blnb, I_bw1, I_bb1, I_bw2, I_bb2;
    if (in_sizes[3] == 4096) {  // dict order
        I_node = 0; I_q = 1; I_edge = 2; I_loc = 3; I_ptr = 4; I_eb = 5; I_mask = 6; I_eidx = 7;
        I_ln1g = 8; I_ln1b = 9; I_zw1 = 10; I_zb1 = 11; I_zw2 = 12; I_zb2 = 13;
        I_cw1 = 14; I_cb1 = 15; I_cw2 = 16; I_cb2 = 17;
        I_blng = 18; I_blnb = 19; I_bw1 = 20; I_bb1 = 21; I_bw2 = 22; I_bb2 = 23;
    } else {                    // signature order
        I_node = 0; I_q = 1; I_edge = 2;
        I_ln1g = 3; I_ln1b = 4; I_zw1 = 5; I_zb1 = 6; I_zw2 = 7; I_zb2 = 8;
        I_cw1 = 9; I_cb1 = 10; I_cw2 = 11; I_cb2 = 12;
        I_blng = 13; I_blnb = 14; I_bw1 = 15; I_bb1 = 16; I_bw2 = 17; I_bb2 = 18;
        I_loc = 19; I_ptr = 20; I_eb = 21; I_mask = 22; I_eidx = 23;
    }

    const float* nodes = (const float*)d_in[I_node];
    const float* qt    = (const float*)d_in[I_q];
    const float* et    = (const float*)d_in[I_edge];
    const int*   locs  = (const int*)d_in[I_loc];
    const int*   ptr   = (const int*)d_in[I_ptr];
    const int*   ebat  = (const int*)d_in[I_eb];
    const int*   mask  = (const int*)d_in[I_mask];
    const int*   eidx  = (const int*)d_in[I_eidx];
    float* out = (float*)d_out;

    int dev = 0, nsm = 148;
    cudaGetDevice(&dev);
    cudaDeviceGetAttribute(&nsm, cudaDevAttrMultiProcessorCount, dev);

    static int smem_set = 0;
    if (!smem_set) {
        cudaFuncSetAttribute(k_edge, cudaFuncAttributeMaxDynamicSharedMemorySize, SM_TOTAL);
        smem_set = 1;
    }

    uint2* p_nbf; uint2* p_qbf;
    float2* p_nst; float2* p_qst;
    cudaGetSymbolAddress((void**)&p_nbf, g_nbf);
    cudaGetSymbolAddress((void**)&p_qbf, g_qbf);
    cudaGetSymbolAddress((void**)&p_nst, g_nstat);
    cudaGetSymbolAddress((void**)&p_qst, g_qstat);

    k_init<<<(NNODES + 255) / 256, 256>>>();
    k_prep<<<128, 384>>>((const float*)d_in[I_bw1], (const float*)d_in[I_blng],
                         (const float*)d_in[I_blnb], (const float*)d_in[I_bb1]);
    k_cvt<<<(NNODES + 7) / 8, 256>>>((const float4*)nodes, p_nbf, p_nst, NNODES);
    k_cvt<<<(Gn + 7) / 8, 256>>>((const float4*)qt, p_qbf, p_qst, Gn);
    k_start<<<Gn, 128>>>(nodes, qt, locs, ptr);
    k_ctx4<<<Gn / 4, 128>>>(qt,
                        (const float*)d_in[I_cw1], (const float*)d_in[I_cb1],
                        (const float*)d_in[I_cw2], (const float*)d_in[I_cb2],
                        (const float*)d_in[I_ln1g], (const float*)d_in[I_ln1b],
                        (const float*)d_in[I_zw1], (const float*)d_in[I_zb1],
                        (const float*)d_in[I_zw2], (const float*)d_in[I_zb2],
                        out);
    k_edge<<<nsm, 512, SM_TOTAL>>>(et, ebat, eidx,
                                   (const float*)d_in[I_bw2], (const float*)d_in[I_bb2]);
    k_lpb<<<((NEDGES + 15) / 16 + 255) / 256, 256>>>(eidx, ebat, mask);
    k_fin<<<1, 1024>>>(out);
}

// round 16
// speedup vs baseline: 1.3241x; 1.1081x over previous
#include <cuda_runtime.h>
#include <cuda_bf16.h>
#include <math.h>
#include <stdint.h>

#define Gn 1024
#define Hn 128
#define NNODES 100000
#define NEDGES 500000
#define EPS_LN 1e-5f
#define TILE 256
#define NT2 ((NEDGES + TILE - 1) / TILE)

// ---------------- device scratch ----------------
__device__ float g_u[Hn];
__device__ float g_vb[Hn];
__device__ uint4 g_Wsw[6144];          // 96KB bf16 W', [chunk][j][64k], XOR-16B swizzle
__device__ uint2 g_nbf[NNODES * 32];   // bf16 node tokens
__device__ uint2 g_qbf[Gn * 32];       // bf16 question tokens
__device__ float2 g_nstat[NNODES];     // per-row (sum, sumsq)
__device__ float2 g_qstat[Gn];
__device__ float g_logits[NEDGES];
__device__ float g_expsum[NNODES];
__device__ float g_lpg[Gn];
__device__ float g_selsum[Gn];

// smem byte offsets for k_edge (total 169984)
#define SM_PU    0
#define SM_PVB   512
#define SM_PW2   1024
#define SM_STAT  1536     // 256 x float2
#define SM_SPART 3584     // 512 x float
#define SM_WH    6144     // 96KB weights
#define SM_A0    104448   // 32KB A buf 0 (256 rows x 128B)
#define SM_A1    137216   // 32KB A buf 1
#define SM_TOTAL 169984

__device__ __forceinline__ uint32_t smem_u32(const void* p) {
    uint32_t a;
    asm("{ .reg .u64 t; cvta.to.shared.u64 t, %1; cvt.u32.u64 %0, t; }" : "=r"(a) : "l"(p));
    return a;
}
#define LDMX4(r, a) \
    asm volatile("ldmatrix.sync.aligned.m8n8.x4.shared.b16 {%0,%1,%2,%3}, [%4];" \
        : "=r"((r)[0]), "=r"((r)[1]), "=r"((r)[2]), "=r"((r)[3]) : "r"(a))
#define CP16(dst, src) \
    asm volatile("cp.async.cg.shared.global [%0], [%1], 16;" :: "r"(dst), "l"(src))
#define CP_COMMIT() asm volatile("cp.async.commit_group;" ::: "memory")
// warp-pair barrier: 64 threads (warps 2m, 2m+1), named barrier id = m+1
#define PAIRBAR(id) asm volatile("bar.sync %0, 64;" :: "r"(id) : "memory")

__device__ __forceinline__ void mma_bf16(float* d, const uint32_t* a, const uint32_t* b) {
    asm volatile("mma.sync.aligned.m16n8k16.row.col.f32.bf16.bf16.f32 "
        "{%0,%1,%2,%3}, {%4,%5,%6,%7}, {%8,%9}, {%0,%1,%2,%3};"
        : "+f"(d[0]), "+f"(d[1]), "+f"(d[2]), "+f"(d[3])
        : "r"(a[0]), "r"(a[1]), "r"(a[2]), "r"(a[3]), "r"(b[0]), "r"(b[1]));
}
__device__ __forceinline__ uint32_t cvt_bf16x2(float hi, float lo) {
    uint32_t r;
    asm("cvt.rn.bf16x2.f32 %0, %1, %2;" : "=r"(r) : "f"(hi), "f"(lo));
    return r;
}
__device__ __forceinline__ float geluf(float x) {
    return 0.5f * x * (1.0f + erff(x * 0.70710678118654752440f));
}

// ---------------- init ----------------
__global__ void k_init() {
    int i = blockIdx.x * blockDim.x + threadIdx.x;
    if (i < NNODES) g_expsum[i] = 0.0f;
    if (i < Gn) { g_lpg[i] = 0.0f; g_selsum[i] = 0.0f; }
}

// ---------------- convert fp32 tokens -> bf16 + per-row LN partial sums ----------------
__global__ void k_cvt(const float4* __restrict__ src, uint2* __restrict__ dst,
                      float2* __restrict__ stat, int nrows) {
    int wid = (blockIdx.x * blockDim.x + threadIdx.x) >> 5;
    int lane = threadIdx.x & 31;
    if (wid >= nrows) return;
    float4 v = src[(size_t)wid * 32 + lane];
    uint2 o;
    o.x = cvt_bf16x2(v.y, v.x);
    o.y = cvt_bf16x2(v.w, v.z);
    dst[(size_t)wid * 32 + lane] = o;
    float s = (v.x + v.y) + (v.z + v.w);
    float q = fmaf(v.x, v.x, fmaf(v.y, v.y, fmaf(v.z, v.z, v.w * v.w)));
    #pragma unroll
    for (int off = 16; off; off >>= 1) {
        s += __shfl_xor_sync(0xffffffffu, s, off);
        q += __shfl_xor_sync(0xffffffffu, q, off);
    }
    if (lane == 0) stat[wid] = make_float2(s, q);
}

// ---------------- prep: W' = g.*W -> bf16 swizzled; u, vb ----------------
__global__ void k_prep(const float* __restrict__ bw1, const float* __restrict__ blng,
                       const float* __restrict__ blnb, const float* __restrict__ bb1) {
    int j = blockIdx.x;     // output 0..127
    int k = threadIdx.x;    // 0..383
    __shared__ float rs[12], rv[12];
    float wraw = bw1[k * Hn + j];
    float wv = blng[k] * wraw;
    float vv = blnb[k] * wraw;
    int chunk = k >> 6, kloc = k & 63;
    uint32_t off = (uint32_t)(chunk * 16384 + j * 128 + ((kloc * 2) ^ ((j & 7) << 4)));
    *(unsigned short*)((char*)g_Wsw + off) = __bfloat16_as_ushort(__float2bfloat16(wv));
    float uu = wv;
    #pragma unroll
    for (int o = 16; o; o >>= 1) {
        uu += __shfl_xor_sync(0xffffffffu, uu, o);
        vv += __shfl_xor_sync(0xffffffffu, vv, o);
    }
    if ((k & 31) == 0) { rs[k >> 5] = uu; rv[k >> 5] = vv; }
    __syncthreads();
    if (k == 0) {
        float U = 0.f, V = 0.f;
        for (int i = 0; i < 12; i++) { U += rs[i]; V += rv[i]; }
        g_u[j] = U;
        g_vb[j] = V + bb1[j];
    }
}

// ---------------- fused start-attention + context MLP + log_z (R13 version) ----------------
__device__ __forceinline__ float bsum128(float v, float* red) {
    #pragma unroll
    for (int o = 16; o; o >>= 1) v += __shfl_xor_sync(0xffffffffu, v, o);
    __syncthreads();
    if ((threadIdx.x & 31) == 0) red[threadIdx.x >> 5] = v;
    __syncthreads();
    return red[0] + red[1] + red[2] + red[3];
}
__global__ void k_sctx(const float* __restrict__ nodes, const float* __restrict__ qt,
                       const int* __restrict__ locals, const int* __restrict__ ptr,
                       const float* __restrict__ cw1, const float* __restrict__ cb1,
                       const float* __restrict__ cw2, const float* __restrict__ cb2,
                       const float* __restrict__ ln1g, const float* __restrict__ ln1b,
                       const float* __restrict__ zw1, const float* __restrict__ zb1,
                       const float* __restrict__ zw2, const float* __restrict__ zb2,
                       float* __restrict__ out) {
    int g = blockIdx.x, t = threadIdx.x;  // 128 threads
    __shared__ float red[4];
    __shared__ float sc[64], salpha[64];
    __shared__ int   sidx[64];
    __shared__ float xin[256];
    __shared__ float h1[128];
    __shared__ float xh[128];
    int s0 = ptr[g], s1e = ptr[g + 1];
    int n = s1e - s0; if (n > 64) n = 64; if (n < 0) n = 0;
    float qv = qt[g * Hn + t];
    for (int s = 0; s < n; s++) {
        int nd = locals[s0 + s];
        if (t == 0) sidx[s] = nd;
        float p = nodes[nd * Hn + t] * qv;
        #pragma unroll
        for (int o = 16; o; o >>= 1) p += __shfl_xor_sync(0xffffffffu, p, o);
        if ((t & 31) == 0) red[t >> 5] = p;
        __syncthreads();
        if (t == 0) sc[s] = (red[0] + red[1] + red[2] + red[3]) * 0.08838834764831843f;
        __syncthreads();
    }
    if (t == 0) {
        float m = -INFINITY;
        for (int s = 0; s < n; s++) m = fmaxf(m, sc[s]);
        float d = 0.0f;
        for (int s = 0; s < n; s++) { float e = expf(sc[s] - m); salpha[s] = e; d += e; }
        float inv = 1.0f / d;
        for (int s = 0; s < n; s++) salpha[s] *= inv;
    }
    __syncthreads();
    float acc = 0.0f;
    for (int s = 0; s < n; s++) acc += salpha[s] * nodes[sidx[s] * Hn + t];
    xin[t] = acc;
    xin[128 + t] = qv;
    __syncthreads();
    float a0 = 0.f, a1 = 0.f, a2 = 0.f, a3 = 0.f;
    #pragma unroll 8
    for (int k = 0; k < 256; k += 4) {
        a0 = fmaf(xin[k + 0], cw1[(k + 0) * Hn + t], a0);
        a1 = fmaf(xin[k + 1], cw1[(k + 1) * Hn + t], a1);
        a2 = fmaf(xin[k + 2], cw1[(k + 2) * Hn + t], a2);
        a3 = fmaf(xin[k + 3], cw1[(k + 3) * Hn + t], a3);
    }
    h1[t] = geluf(cb1[t] + (a0 + a1) + (a2 + a3));
    __syncthreads();
    a0 = 0.f; a1 = 0.f; a2 = 0.f; a3 = 0.f;
    #pragma unroll 8
    for (int k = 0; k < 128; k += 4) {
        a0 = fmaf(h1[k + 0], cw2[(k + 0) * Hn + t], a0);
        a1 = fmaf(h1[k + 1], cw2[(k + 1) * Hn + t], a1);
        a2 = fmaf(h1[k + 2], cw2[(k + 2) * Hn + t], a2);
        a3 = fmaf(h1[k + 3], cw2[(k + 3) * Hn + t], a3);
    }
    float c = cb2[t] + (a0 + a1) + (a2 + a3);
    float mean = bsum128(c, red) * (1.0f / 128.0f);
    float d = c - mean;
    float var = bsum128(d * d, red) * (1.0f / 128.0f);
    xh[t] = d * rsqrtf(var + EPS_LN) * ln1g[t] + ln1b[t];
    __syncthreads();
    a0 = 0.f; a1 = 0.f; a2 = 0.f; a3 = 0.f;
    #pragma unroll 8
    for (int k = 0; k < 128; k += 4) {
        a0 = fmaf(xh[k + 0], zw1[(k + 0) * Hn + t], a0);
        a1 = fmaf(xh[k + 1], zw1[(k + 1) * Hn + t], a1);
        a2 = fmaf(xh[k + 2], zw1[(k + 2) * Hn + t], a2);
        a3 = fmaf(xh[k + 3], zw1[(k + 3) * Hn + t], a3);
    }
    float p = geluf(zb1[t] + (a0 + a1) + (a2 + a3)) * zw2[t];
    float lz = bsum128(p, red);
    if (t == 0) out[g * 3 + 0] = lz + zb2[0];
}

// ---------------- edge logits: bf16 GEMM (R13 structure, frozen) ----------------
__global__ void __launch_bounds__(512, 1)
k_edge(const float* __restrict__ et,
       const int* __restrict__ ebatch, const int* __restrict__ eidx,
       const float* __restrict__ bw2, const float* __restrict__ bb2) {
    extern __shared__ char smem[];
    uint32_t sb = smem_u32(smem);
    int t = threadIdx.x, lane = t & 31;
    int w = t >> 5;
    int warp_m = w >> 1, warp_n = w & 1;
    int pb = warp_m + 1;            // named barrier id for this warp pair (1..8)

    // stage weights + params
    {
        uint4* dh = (uint4*)(smem + SM_WH);
        for (int i = t; i < 6144; i += 512) dh[i] = g_Wsw[i];
    }
    float* pu  = (float*)(smem + SM_PU);
    float* pvb = (float*)(smem + SM_PVB);
    float* pw2 = (float*)(smem + SM_PW2);
    float2* st = (float2*)(smem + SM_STAT);
    float* spart = (float*)(smem + SM_SPART);
    if (t < 128) { pu[t] = g_u[t]; pvb[t] = g_vb[t]; pw2[t] = bw2[t]; }
    __syncthreads();
    float bias2 = bb2[0];

    int r = t >> 1;                 // my row (0..255), 2 threads per row
    int hh = t & 1;                 // which half of the 64-float chunk
    uint32_t swrow = (uint32_t)((r & 7) << 4);
    uint32_t dst0 = sb + SM_A0 + r * 128;
    uint32_t dst1 = sb + SM_A1 + r * 128;

    for (int tile = blockIdx.x; tile < NT2; tile += gridDim.x) {
        int e0 = tile * TILE;
        int e = e0 + r; if (e >= NEDGES) e = NEDGES - 1;
        int br = ebatch[e], tgr = eidx[NEDGES + e];
        const char* srcQ = (const char*)(g_qbf + (size_t)br * 32);
        const char* srcN = (const char*)(g_nbf + (size_t)tgr * 32);

        // ---- edge tokens: fp32 LDG -> cvt -> STS (chunks 0,1), stats in-flight ----
        const float4* srcE = (const float4*)(et + (size_t)e * Hn) + hh * 8;
        float eS = 0.0f, eQ = 0.0f;
        #pragma unroll
        for (int c01 = 0; c01 < 2; c01++) {
            float4 fv[8];
            #pragma unroll
            for (int i = 0; i < 8; i++) fv[i] = srcE[c01 * 16 + i];
            uint32_t dst = c01 ? dst1 : dst0;
            #pragma unroll
            for (int i = 0; i < 8; i++) {
                float4 v = fv[i];
                eS += (v.x + v.y) + (v.z + v.w);
                eQ += fmaf(v.x, v.x, fmaf(v.y, v.y, fmaf(v.z, v.z, v.w * v.w)));
                uint2 H;
                H.x = cvt_bf16x2(v.y, v.x);
                H.y = cvt_bf16x2(v.w, v.z);
                uint32_t off = (uint32_t)((hh * 64 + i * 8) ^ swrow);
                *(uint2*)(smem + (dst - sb) + off) = H;
            }
        }
        // row LN stats: edge part (2-thread reduce) + node/question tables
        eS += __shfl_xor_sync(0xffffffffu, eS, 1);
        eQ += __shfl_xor_sync(0xffffffffu, eQ, 1);
        if (hh == 0) {
            float2 bq = g_qstat[br];
            float2 cn = g_nstat[tgr];
            st[r] = make_float2(eS + bq.x + cn.x, eQ + bq.y + cn.y);
        }

        float acc[2][8][4];
        #pragma unroll
        for (int a = 0; a < 2; a++)
            #pragma unroll
            for (int b = 0; b < 8; b++)
                #pragma unroll
                for (int d = 0; d < 4; d++) acc[a][b][d] = 0.0f;

        // ---- pipeline: pair-local sync; MMA c, then cp.async c+2 ----
        #pragma unroll 1
        for (int c = 0; c < 6; c++) {
            if (c >= 2) {
                if (c < 5) asm volatile("cp.async.wait_group 1;" ::: "memory");
                else       asm volatile("cp.async.wait_group 0;" ::: "memory");
            }
            PAIRBAR(pb);   // A rows [32*warp_m, +32) produced by this pair only
            uint32_t whc = sb + SM_WH + c * 16384;
            uint32_t abb = sb + ((c & 1) ? SM_A1 : SM_A0);
            #pragma unroll
            for (int ks = 0; ks < 4; ks++) {
                uint32_t ah[2][4], bh[16];
                #pragma unroll
                for (int mt = 0; mt < 2; mt++) {
                    int row = warp_m * 32 + mt * 16 + (lane & 7) + ((lane >> 3) & 1) * 8;
                    int colb = ks * 32 + (lane >> 4) * 16;
                    LDMX4(ah[mt], abb + (uint32_t)(row * 128 + (colb ^ ((row & 7) << 4))));
                }
                #pragma unroll
                for (int bt = 0; bt < 4; bt++) {
                    int j = warp_n * 64 + bt * 16 + (lane & 7) + (lane >> 4) * 8;
                    int kb = ks * 32 + ((lane >> 3) & 1) * 16;
                    LDMX4(&bh[bt * 4], whc + (uint32_t)(j * 128 + (kb ^ ((j & 7) << 4))));
                }
                #pragma unroll
                for (int mt = 0; mt < 2; mt++)
                    #pragma unroll
                    for (int nt = 0; nt < 8; nt++)
                        mma_bf16(acc[mt][nt], ah[mt], &bh[(nt >> 1) * 4 + (nt & 1) * 2]);
            }
            PAIRBAR(pb);   // pair done reading buf (c&1) before refilling it
            if (c < 4) {
                int cn = c + 2;
                int part = cn >> 1, half = cn & 1;
                const char* srcp = (part == 1) ? srcQ : srcN;
                uint32_t dst = (cn & 1) ? dst1 : dst0;
                #pragma unroll
                for (int i = 0; i < 4; i++) {
                    int sg = hh * 4 + i;
                    CP16(dst + ((sg * 16) ^ swrow), srcp + half * 128 + sg * 16);
                }
                CP_COMMIT();
            }
        }

        // epilogue: folded LN + GELU + dot(w2); fused node expsum atomic
        int gq = lane >> 2, cpair = (lane & 3) * 2;
        #pragma unroll
        for (int mt = 0; mt < 2; mt++) {
            #pragma unroll
            for (int half = 0; half < 2; half++) {
                int row = warp_m * 32 + mt * 16 + half * 8 + gq;
                float2 sv = st[row];
                float m = sv.x * (1.0f / 384.0f);
                float var = sv.y * (1.0f / 384.0f) - m * m;
                float is = rsqrtf(fmaxf(var, 0.0f) + EPS_LN);
                float pv = 0.0f;
                #pragma unroll
                for (int nt = 0; nt < 8; nt++) {
                    int j0 = warp_n * 64 + nt * 8 + cpair;
                    float d0 = acc[mt][nt][half * 2 + 0];
                    float d1 = acc[mt][nt][half * 2 + 1];
                    float y0 = (d0 - m * pu[j0])     * is + pvb[j0];
                    float y1 = (d1 - m * pu[j0 + 1]) * is + pvb[j0 + 1];
                    pv = fmaf(geluf(y0), pw2[j0], pv);
                    pv = fmaf(geluf(y1), pw2[j0 + 1], pv);
                }
                pv += __shfl_xor_sync(0xffffffffu, pv, 1);
                pv += __shfl_xor_sync(0xffffffffu, pv, 2);
                if ((lane & 3) == 0) spart[warp_n * 256 + row] = pv;
            }
        }
        __syncthreads();
        if (t < 256) {
            int e2 = e0 + t;
            if (e2 < NEDGES) {
                float L = spart[t] + spart[256 + t] + bias2;
                g_logits[e2] = L;
                atomicAdd(&g_expsum[eidx[NEDGES + e2]], expf(L));
            }
        }
        __syncthreads();
    }
}

// ---------------- per-graph selected log-prob sums ----------------
__global__ void k_lpb(const int* __restrict__ eidx, const int* __restrict__ ebatch,
                      const int* __restrict__ mask) {
    const int CH = 16;
    int base = (blockIdx.x * blockDim.x + threadIdx.x) * CH;
    if (base >= NEDGES) return;
    int end = base + CH; if (end > NEDGES) end = NEDGES;
    int cur = -1; float aL = 0.0f, aS = 0.0f;
    for (int e = base; e < end; e++) {
        int b = ebatch[e];
        if (b != cur) {
            if (cur >= 0 && (aL != 0.0f || aS != 0.0f)) {
                atomicAdd(&g_lpg[cur], aL);
                atomicAdd(&g_selsum[cur], aS);
            }
            cur = b; aL = 0.0f; aS = 0.0f;
        }
        if (mask[e] != 0) {
            int tg = eidx[NEDGES + e];
            float lp = g_logits[e] - logf(g_expsum[tg]);
            aL += lp; aS += 1.0f;
        }
    }
    if (cur >= 0 && (aL != 0.0f || aS != 0.0f)) {
        atomicAdd(&g_lpg[cur], aL);
        atomicAdd(&g_selsum[cur], aS);
    }
}
__global__ void k_fin(float* __restrict__ out) {
    int g = threadIdx.x;
    __shared__ float rs[32], rc[32];
    __shared__ float s_res;
    float lpg = g_lpg[g];
    float has = (g_selsum[g] > 0.0f) ? 1.0f : 0.0f;
    float v1 = -lpg * has, v2 = has;
    #pragma unroll
    for (int o = 16; o; o >>= 1) {
        v1 += __shfl_xor_sync(0xffffffffu, v1, o);
        v2 += __shfl_xor_sync(0xffffffffu, v2, o);
    }
    if ((g & 31) == 0) { rs[g >> 5] = v1; rc[g >> 5] = v2; }
    __syncthreads();
    if (g < 32) {
        float a = rs[g], b = rc[g];
        #pragma unroll
        for (int o = 16; o; o >>= 1) {
            a += __shfl_xor_sync(0xffffffffu, a, o);
            b += __shfl_xor_sync(0xffffffffu, b, o);
        }
        if (g == 0) s_res = a / fmaxf(b, 1.0f);
    }
    __syncthreads();
    out[g * 3 + 1] = lpg;
    out[g * 3 + 2] = s_res;
}

// ---------------- host ----------------
extern "C" void kernel_launch(void* const* d_in, const int* in_sizes, int n_in,
                              void* d_out, int out_size) {
    int I_node, I_q, I_edge, I_loc, I_ptr, I_eb, I_mask, I_eidx;
    int I_ln1g, I_ln1b, I_zw1, I_zb1, I_zw2, I_zb2;
    int I_cw1, I_cb1, I_cw2, I_cb2, I_blng, I_blnb, I_bw1, I_bb1, I_bw2, I_bb2;
    if (in_sizes[3] == 4096) {  // dict order
        I_node = 0; I_q = 1; I_edge = 2; I_loc = 3; I_ptr = 4; I_eb = 5; I_mask = 6; I_eidx = 7;
        I_ln1g = 8; I_ln1b = 9; I_zw1 = 10; I_zb1 = 11; I_zw2 = 12; I_zb2 = 13;
        I_cw1 = 14; I_cb1 = 15; I_cw2 = 16; I_cb2 = 17;
        I_blng = 18; I_blnb = 19; I_bw1 = 20; I_bb1 = 21; I_bw2 = 22; I_bb2 = 23;
    } else {                    // signature order
        I_node = 0; I_q = 1; I_edge = 2;
        I_ln1g = 3; I_ln1b = 4; I_zw1 = 5; I_zb1 = 6; I_zw2 = 7; I_zb2 = 8;
        I_cw1 = 9; I_cb1 = 10; I_cw2 = 11; I_cb2 = 12;
        I_blng = 13; I_blnb = 14; I_bw1 = 15; I_bb1 = 16; I_bw2 = 17; I_bb2 = 18;
        I_loc = 19; I_ptr = 20; I_eb = 21; I_mask = 22; I_eidx = 23;
    }

    const float* nodes = (const float*)d_in[I_node];
    const float* qt    = (const float*)d_in[I_q];
    const float* et    = (const float*)d_in[I_edge];
    const int*   locs  = (const int*)d_in[I_loc];
    const int*   ptr   = (const int*)d_in[I_ptr];
    const int*   ebat  = (const int*)d_in[I_eb];
    const int*   mask  = (const int*)d_in[I_mask];
    const int*   eidx  = (const int*)d_in[I_eidx];
    float* out = (float*)d_out;

    int dev = 0, nsm = 148;
    cudaGetDevice(&dev);
    cudaDeviceGetAttribute(&nsm, cudaDevAttrMultiProcessorCount, dev);

    static int smem_set = 0;
    static cudaStream_t s2 = 0;
    static cudaEvent_t ev_fork = 0, ev_join = 0;
    if (!smem_set) {
        cudaFuncSetAttribute(k_edge, cudaFuncAttributeMaxDynamicSharedMemorySize, SM_TOTAL);
        cudaStreamCreateWithFlags(&s2, cudaStreamNonBlocking);
        cudaEventCreateWithFlags(&ev_fork, cudaEventDisableTiming);
        cudaEventCreateWithFlags(&ev_join, cudaEventDisableTiming);
        smem_set = 1;
    }

    uint2* p_nbf; uint2* p_qbf;
    float2* p_nst; float2* p_qst;
    cudaGetSymbolAddress((void**)&p_nbf, g_nbf);
    cudaGetSymbolAddress((void**)&p_qbf, g_qbf);
    cudaGetSymbolAddress((void**)&p_nst, g_nstat);
    cudaGetSymbolAddress((void**)&p_qst, g_qstat);

    // fork: k_sctx is independent of the k_edge prerequisite chain — run it on s2
    cudaEventRecord(ev_fork, 0);
    cudaStreamWaitEvent(s2, ev_fork, 0);
    k_sctx<<<Gn, 128, 0, s2>>>(nodes, qt, locs, ptr,
                        (const float*)d_in[I_cw1], (const float*)d_in[I_cb1],
                        (const float*)d_in[I_cw2], (const float*)d_in[I_cb2],
                        (const float*)d_in[I_ln1g], (const float*)d_in[I_ln1b],
                        (const float*)d_in[I_zw1], (const float*)d_in[I_zb1],
                        (const float*)d_in[I_zw2], (const float*)d_in[I_zb2],
                        out);
    cudaEventRecord(ev_join, s2);

    // main chain
    k_init<<<(NNODES + 255) / 256, 256>>>();
    k_prep<<<128, 384>>>((const float*)d_in[I_bw1], (const float*)d_in[I_blng],
                         (const float*)d_in[I_blnb], (const float*)d_in[I_bb1]);
    k_cvt<<<(NNODES + 7) / 8, 256>>>((const float4*)nodes, p_nbf, p_nst, NNODES);
    k_cvt<<<(Gn + 7) / 8, 256>>>((const float4*)qt, p_qbf, p_qst, Gn);
    k_edge<<<nsm, 512, SM_TOTAL>>>(et, ebat, eidx,
                                   (const float*)d_in[I_bw2], (const float*)d_in[I_bb2]);
    k_lpb<<<((NEDGES + 15) / 16 + 255) / 256, 256>>>(eidx, ebat, mask);
    // join before final output kernel (out[:,0] written on s2)
    cudaStreamWaitEvent(0, ev_join, 0);
    k_fin<<<1, 1024>>>(out);
}

// round 17
// speedup vs baseline: 1.3458x; 1.0163x over previous
#include <cuda_runtime.h>
#include <cuda_bf16.h>
#include <math.h>
#include <stdint.h>

#define Gn 1024
#define Hn 128
#define NNODES 100000
#define NEDGES 500000
#define EPS_LN 1e-5f
#define TILE 256
#define NT2 ((NEDGES + TILE - 1) / TILE)

// ---------------- device scratch ----------------
__device__ float g_u[Hn];
__device__ float g_vb[Hn];
__device__ uint4 g_Wsw[6144];          // 96KB bf16 W', [chunk][j][64k], XOR-16B swizzle
__device__ uint2 g_nbf[NNODES * 32];   // bf16 node tokens
__device__ uint2 g_qbf[Gn * 32];       // bf16 question tokens
__device__ float2 g_nstat[NNODES];     // per-row (sum, sumsq)
__device__ float2 g_qstat[Gn];
__device__ float g_logits[NEDGES];
__device__ float g_expsum[NNODES];
__device__ float g_lpg[Gn];
__device__ float g_selsum[Gn];

// smem byte offsets for k_edge (total 169984)
#define SM_PU    0
#define SM_PVB   512
#define SM_PW2   1024
#define SM_STAT  1536     // 256 x float2
#define SM_SPART 3584     // 512 x float
#define SM_WH    6144     // 96KB weights
#define SM_A0    104448   // 32KB A buf 0 (256 rows x 128B)
#define SM_A1    137216   // 32KB A buf 1
#define SM_TOTAL 169984

__device__ __forceinline__ uint32_t smem_u32(const void* p) {
    uint32_t a;
    asm("{ .reg .u64 t; cvta.to.shared.u64 t, %1; cvt.u32.u64 %0, t; }" : "=r"(a) : "l"(p));
    return a;
}
#define LDMX4(r, a) \
    asm volatile("ldmatrix.sync.aligned.m8n8.x4.shared.b16 {%0,%1,%2,%3}, [%4];" \
        : "=r"((r)[0]), "=r"((r)[1]), "=r"((r)[2]), "=r"((r)[3]) : "r"(a))
#define CP16(dst, src) \
    asm volatile("cp.async.cg.shared.global [%0], [%1], 16;" :: "r"(dst), "l"(src))
#define CP_COMMIT() asm volatile("cp.async.commit_group;" ::: "memory")
// warp-pair barrier: 64 threads (warps 2m, 2m+1), named barrier id = m+1
#define PAIRBAR(id) asm volatile("bar.sync %0, 64;" :: "r"(id) : "memory")

__device__ __forceinline__ void mma_bf16(float* d, const uint32_t* a, const uint32_t* b) {
    asm volatile("mma.sync.aligned.m16n8k16.row.col.f32.bf16.bf16.f32 "
        "{%0,%1,%2,%3}, {%4,%5,%6,%7}, {%8,%9}, {%0,%1,%2,%3};"
        : "+f"(d[0]), "+f"(d[1]), "+f"(d[2]), "+f"(d[3])
        : "r"(a[0]), "r"(a[1]), "r"(a[2]), "r"(a[3]), "r"(b[0]), "r"(b[1]));
}
__device__ __forceinline__ uint32_t cvt_bf16x2(float hi, float lo) {
    uint32_t r;
    asm("cvt.rn.bf16x2.f32 %0, %1, %2;" : "=r"(r) : "f"(hi), "f"(lo));
    return r;
}
__device__ __forceinline__ float geluf(float x) {
    return 0.5f * x * (1.0f + erff(x * 0.70710678118654752440f));
}

// ---------------- init (per-graph accumulators only) ----------------
__global__ void k_init() {
    int i = blockIdx.x * blockDim.x + threadIdx.x;
    if (i < Gn) { g_lpg[i] = 0.0f; g_selsum[i] = 0.0f; }
}

// ---------------- convert fp32 tokens -> bf16 + per-row LN partial sums ----------------
// expsum != nullptr: also zero the per-node expsum accumulator (same row space)
__global__ void k_cvt(const float4* __restrict__ src, uint2* __restrict__ dst,
                      float2* __restrict__ stat, float* __restrict__ expsum, int nrows) {
    int wid = (blockIdx.x * blockDim.x + threadIdx.x) >> 5;
    int lane = threadIdx.x & 31;
    if (wid >= nrows) return;
    float4 v = src[(size_t)wid * 32 + lane];
    uint2 o;
    o.x = cvt_bf16x2(v.y, v.x);
    o.y = cvt_bf16x2(v.w, v.z);
    dst[(size_t)wid * 32 + lane] = o;
    float s = (v.x + v.y) + (v.z + v.w);
    float q = fmaf(v.x, v.x, fmaf(v.y, v.y, fmaf(v.z, v.z, v.w * v.w)));
    #pragma unroll
    for (int off = 16; off; off >>= 1) {
        s += __shfl_xor_sync(0xffffffffu, s, off);
        q += __shfl_xor_sync(0xffffffffu, q, off);
    }
    if (lane == 0) {
        stat[wid] = make_float2(s, q);
        if (expsum) expsum[wid] = 0.0f;
    }
}

// ---------------- prep: W' = g.*W -> bf16 swizzled; u, vb ----------------
__global__ void k_prep(const float* __restrict__ bw1, const float* __restrict__ blng,
                       const float* __restrict__ blnb, const float* __restrict__ bb1) {
    int j = blockIdx.x;     // output 0..127
    int k = threadIdx.x;    // 0..383
    __shared__ float rs[12], rv[12];
    float wraw = bw1[k * Hn + j];
    float wv = blng[k] * wraw;
    float vv = blnb[k] * wraw;
    int chunk = k >> 6, kloc = k & 63;
    uint32_t off = (uint32_t)(chunk * 16384 + j * 128 + ((kloc * 2) ^ ((j & 7) << 4)));
    *(unsigned short*)((char*)g_Wsw + off) = __bfloat16_as_ushort(__float2bfloat16(wv));
    float uu = wv;
    #pragma unroll
    for (int o = 16; o; o >>= 1) {
        uu += __shfl_xor_sync(0xffffffffu, uu, o);
        vv += __shfl_xor_sync(0xffffffffu, vv, o);
    }
    if ((k & 31) == 0) { rs[k >> 5] = uu; rv[k >> 5] = vv; }
    __syncthreads();
    if (k == 0) {
        float U = 0.f, V = 0.f;
        for (int i = 0; i < 12; i++) { U += rs[i]; V += rv[i]; }
        g_u[j] = U;
        g_vb[j] = V + bb1[j];
    }
}

// ---------------- fused start-attention + context MLP + log_z (R13 version) ----------------
__device__ __forceinline__ float bsum128(float v, float* red) {
    #pragma unroll
    for (int o = 16; o; o >>= 1) v += __shfl_xor_sync(0xffffffffu, v, o);
    __syncthreads();
    if ((threadIdx.x & 31) == 0) red[threadIdx.x >> 5] = v;
    __syncthreads();
    return red[0] + red[1] + red[2] + red[3];
}
__global__ void k_sctx(const float* __restrict__ nodes, const float* __restrict__ qt,
                       const int* __restrict__ locals, const int* __restrict__ ptr,
                       const float* __restrict__ cw1, const float* __restrict__ cb1,
                       const float* __restrict__ cw2, const float* __restrict__ cb2,
                       const float* __restrict__ ln1g, const float* __restrict__ ln1b,
                       const float* __restrict__ zw1, const float* __restrict__ zb1,
                       const float* __restrict__ zw2, const float* __restrict__ zb2,
                       float* __restrict__ out) {
    int g = blockIdx.x, t = threadIdx.x;  // 128 threads
    __shared__ float red[4];
    __shared__ float sc[64], salpha[64];
    __shared__ int   sidx[64];
    __shared__ float xin[256];
    __shared__ float h1[128];
    __shared__ float xh[128];
    int s0 = ptr[g], s1e = ptr[g + 1];
    int n = s1e - s0; if (n > 64) n = 64; if (n < 0) n = 0;
    float qv = qt[g * Hn + t];
    for (int s = 0; s < n; s++) {
        int nd = locals[s0 + s];
        if (t == 0) sidx[s] = nd;
        float p = nodes[nd * Hn + t] * qv;
        #pragma unroll
        for (int o = 16; o; o >>= 1) p += __shfl_xor_sync(0xffffffffu, p, o);
        if ((t & 31) == 0) red[t >> 5] = p;
        __syncthreads();
        if (t == 0) sc[s] = (red[0] + red[1] + red[2] + red[3]) * 0.08838834764831843f;
        __syncthreads();
    }
    if (t == 0) {
        float m = -INFINITY;
        for (int s = 0; s < n; s++) m = fmaxf(m, sc[s]);
        float d = 0.0f;
        for (int s = 0; s < n; s++) { float e = expf(sc[s] - m); salpha[s] = e; d += e; }
        float inv = 1.0f / d;
        for (int s = 0; s < n; s++) salpha[s] *= inv;
    }
    __syncthreads();
    float acc = 0.0f;
    for (int s = 0; s < n; s++) acc += salpha[s] * nodes[sidx[s] * Hn + t];
    xin[t] = acc;
    xin[128 + t] = qv;
    __syncthreads();
    float a0 = 0.f, a1 = 0.f, a2 = 0.f, a3 = 0.f;
    #pragma unroll 8
    for (int k = 0; k < 256; k += 4) {
        a0 = fmaf(xin[k + 0], cw1[(k + 0) * Hn + t], a0);
        a1 = fmaf(xin[k + 1], cw1[(k + 1) * Hn + t], a1);
        a2 = fmaf(xin[k + 2], cw1[(k + 2) * Hn + t], a2);
        a3 = fmaf(xin[k + 3], cw1[(k + 3) * Hn + t], a3);
    }
    h1[t] = geluf(cb1[t] + (a0 + a1) + (a2 + a3));
    __syncthreads();
    a0 = 0.f; a1 = 0.f; a2 = 0.f; a3 = 0.f;
    #pragma unroll 8
    for (int k = 0; k < 128; k += 4) {
        a0 = fmaf(h1[k + 0], cw2[(k + 0) * Hn + t], a0);
        a1 = fmaf(h1[k + 1], cw2[(k + 1) * Hn + t], a1);
        a2 = fmaf(h1[k + 2], cw2[(k + 2) * Hn + t], a2);
        a3 = fmaf(h1[k + 3], cw2[(k + 3) * Hn + t], a3);
    }
    float c = cb2[t] + (a0 + a1) + (a2 + a3);
    float mean = bsum128(c, red) * (1.0f / 128.0f);
    float d = c - mean;
    float var = bsum128(d * d, red) * (1.0f / 128.0f);
    xh[t] = d * rsqrtf(var + EPS_LN) * ln1g[t] + ln1b[t];
    __syncthreads();
    a0 = 0.f; a1 = 0.f; a2 = 0.f; a3 = 0.f;
    #pragma unroll 8
    for (int k = 0; k < 128; k += 4) {
        a0 = fmaf(xh[k + 0], zw1[(k + 0) * Hn + t], a0);
        a1 = fmaf(xh[k + 1], zw1[(k + 1) * Hn + t], a1);
        a2 = fmaf(xh[k + 2], zw1[(k + 2) * Hn + t], a2);
        a3 = fmaf(xh[k + 3], zw1[(k + 3) * Hn + t], a3);
    }
    float p = geluf(zb1[t] + (a0 + a1) + (a2 + a3)) * zw2[t];
    float lz = bsum128(p, red);
    if (t == 0) out[g * 3 + 0] = lz + zb2[0];
}

// ---------------- edge logits: bf16 GEMM (R13 structure, frozen) ----------------
__global__ void __launch_bounds__(512, 1)
k_edge(const float* __restrict__ et,
       const int* __restrict__ ebatch, const int* __restrict__ eidx,
       const float* __restrict__ bw2, const float* __restrict__ bb2) {
    extern __shared__ char smem[];
    uint32_t sb = smem_u32(smem);
    int t = threadIdx.x, lane = t & 31;
    int w = t >> 5;
    int warp_m = w >> 1, warp_n = w & 1;
    int pb = warp_m + 1;            // named barrier id for this warp pair (1..8)

    // stage weights + params
    {
        uint4* dh = (uint4*)(smem + SM_WH);
        for (int i = t; i < 6144; i += 512) dh[i] = g_Wsw[i];
    }
    float* pu  = (float*)(smem + SM_PU);
    float* pvb = (float*)(smem + SM_PVB);
    float* pw2 = (float*)(smem + SM_PW2);
    float2* st = (float2*)(smem + SM_STAT);
    float* spart = (float*)(smem + SM_SPART);
    if (t < 128) { pu[t] = g_u[t]; pvb[t] = g_vb[t]; pw2[t] = bw2[t]; }
    __syncthreads();
    float bias2 = bb2[0];

    int r = t >> 1;                 // my row (0..255), 2 threads per row
    int hh = t & 1;                 // which half of the 64-float chunk
    uint32_t swrow = (uint32_t)((r & 7) << 4);
    uint32_t dst0 = sb + SM_A0 + r * 128;
    uint32_t dst1 = sb + SM_A1 + r * 128;

    for (int tile = blockIdx.x; tile < NT2; tile += gridDim.x) {
        int e0 = tile * TILE;
        int e = e0 + r; if (e >= NEDGES) e = NEDGES - 1;
        int br = ebatch[e], tgr = eidx[NEDGES + e];
        const char* srcQ = (const char*)(g_qbf + (size_t)br * 32);
        const char* srcN = (const char*)(g_nbf + (size_t)tgr * 32);

        // ---- edge tokens: fp32 LDG -> cvt -> STS (chunks 0,1), stats in-flight ----
        const float4* srcE = (const float4*)(et + (size_t)e * Hn) + hh * 8;
        float eS = 0.0f, eQ = 0.0f;
        #pragma unroll
        for (int c01 = 0; c01 < 2; c01++) {
            float4 fv[8];
            #pragma unroll
            for (int i = 0; i < 8; i++) fv[i] = srcE[c01 * 16 + i];
            uint32_t dst = c01 ? dst1 : dst0;
            #pragma unroll
            for (int i = 0; i < 8; i++) {
                float4 v = fv[i];
                eS += (v.x + v.y) + (v.z + v.w);
                eQ += fmaf(v.x, v.x, fmaf(v.y, v.y, fmaf(v.z, v.z, v.w * v.w)));
                uint2 H;
                H.x = cvt_bf16x2(v.y, v.x);
                H.y = cvt_bf16x2(v.w, v.z);
                uint32_t off = (uint32_t)((hh * 64 + i * 8) ^ swrow);
                *(uint2*)(smem + (dst - sb) + off) = H;
            }
        }
        // row LN stats: edge part (2-thread reduce) + node/question tables
        eS += __shfl_xor_sync(0xffffffffu, eS, 1);
        eQ += __shfl_xor_sync(0xffffffffu, eQ, 1);
        if (hh == 0) {
            float2 bq = g_qstat[br];
            float2 cn = g_nstat[tgr];
            st[r] = make_float2(eS + bq.x + cn.x, eQ + bq.y + cn.y);
        }

        float acc[2][8][4];
        #pragma unroll
        for (int a = 0; a < 2; a++)
            #pragma unroll
            for (int b = 0; b < 8; b++)
                #pragma unroll
                for (int d = 0; d < 4; d++) acc[a][b][d] = 0.0f;

        // ---- pipeline: pair-local sync; MMA c, then cp.async c+2 ----
        #pragma unroll 1
        for (int c = 0; c < 6; c++) {
            if (c >= 2) {
                if (c < 5) asm volatile("cp.async.wait_group 1;" ::: "memory");
                else       asm volatile("cp.async.wait_group 0;" ::: "memory");
            }
            PAIRBAR(pb);   // A rows [32*warp_m, +32) produced by this pair only
            uint32_t whc = sb + SM_WH + c * 16384;
            uint32_t abb = sb + ((c & 1) ? SM_A1 : SM_A0);
            #pragma unroll
            for (int ks = 0; ks < 4; ks++) {
                uint32_t ah[2][4], bh[16];
                #pragma unroll
                for (int mt = 0; mt < 2; mt++) {
                    int row = warp_m * 32 + mt * 16 + (lane & 7) + ((lane >> 3) & 1) * 8;
                    int colb = ks * 32 + (lane >> 4) * 16;
                    LDMX4(ah[mt], abb + (uint32_t)(row * 128 + (colb ^ ((row & 7) << 4))));
                }
                #pragma unroll
                for (int bt = 0; bt < 4; bt++) {
                    int j = warp_n * 64 + bt * 16 + (lane & 7) + (lane >> 4) * 8;
                    int kb = ks * 32 + ((lane >> 3) & 1) * 16;
                    LDMX4(&bh[bt * 4], whc + (uint32_t)(j * 128 + (kb ^ ((j & 7) << 4))));
                }
                #pragma unroll
                for (int mt = 0; mt < 2; mt++)
                    #pragma unroll
                    for (int nt = 0; nt < 8; nt++)
                        mma_bf16(acc[mt][nt], ah[mt], &bh[(nt >> 1) * 4 + (nt & 1) * 2]);
            }
            PAIRBAR(pb);   // pair done reading buf (c&1) before refilling it
            if (c < 4) {
                int cn = c + 2;
                int part = cn >> 1, half = cn & 1;
                const char* srcp = (part == 1) ? srcQ : srcN;
                uint32_t dst = (cn & 1) ? dst1 : dst0;
                #pragma unroll
                for (int i = 0; i < 4; i++) {
                    int sg = hh * 4 + i;
                    CP16(dst + ((sg * 16) ^ swrow), srcp + half * 128 + sg * 16);
                }
                CP_COMMIT();
            }
        }

        // epilogue: folded LN + GELU + dot(w2); fused node expsum atomic
        int gq = lane >> 2, cpair = (lane & 3) * 2;
        #pragma unroll
        for (int mt = 0; mt < 2; mt++) {
            #pragma unroll
            for (int half = 0; half < 2; half++) {
                int row = warp_m * 32 + mt * 16 + half * 8 + gq;
                float2 sv = st[row];
                float m = sv.x * (1.0f / 384.0f);
                float var = sv.y * (1.0f / 384.0f) - m * m;
                float is = rsqrtf(fmaxf(var, 0.0f) + EPS_LN);
                float pv = 0.0f;
                #pragma unroll
                for (int nt = 0; nt < 8; nt++) {
                    int j0 = warp_n * 64 + nt * 8 + cpair;
                    float d0 = acc[mt][nt][half * 2 + 0];
                    float d1 = acc[mt][nt][half * 2 + 1];
                    float y0 = (d0 - m * pu[j0])     * is + pvb[j0];
                    float y1 = (d1 - m * pu[j0 + 1]) * is + pvb[j0 + 1];
                    pv = fmaf(geluf(y0), pw2[j0], pv);
                    pv = fmaf(geluf(y1), pw2[j0 + 1], pv);
                }
                pv += __shfl_xor_sync(0xffffffffu, pv, 1);
                pv += __shfl_xor_sync(0xffffffffu, pv, 2);
                if ((lane & 3) == 0) spart[warp_n * 256 + row] = pv;
            }
        }
        __syncthreads();
        if (t < 256) {
            int e2 = e0 + t;
            if (e2 < NEDGES) {
                float L = spart[t] + spart[256 + t] + bias2;
                g_logits[e2] = L;
                atomicAdd(&g_expsum[eidx[NEDGES + e2]], expf(L));
            }
        }
        __syncthreads();
    }
}

// ---------------- per-graph selected log-prob sums ----------------
__global__ void k_lpb(const int* __restrict__ eidx, const int* __restrict__ ebatch,
                      const int* __restrict__ mask) {
    const int CH = 16;
    int base = (blockIdx.x * blockDim.x + threadIdx.x) * CH;
    if (base >= NEDGES) return;
    int end = base + CH; if (end > NEDGES) end = NEDGES;
    int cur = -1; float aL = 0.0f, aS = 0.0f;
    for (int e = base; e < end; e++) {
        int b = ebatch[e];
        if (b != cur) {
            if (cur >= 0 && (aL != 0.0f || aS != 0.0f)) {
                atomicAdd(&g_lpg[cur], aL);
                atomicAdd(&g_selsum[cur], aS);
            }
            cur = b; aL = 0.0f; aS = 0.0f;
        }
        if (mask[e] != 0) {
            int tg = eidx[NEDGES + e];
            float lp = g_logits[e] - logf(g_expsum[tg]);
            aL += lp; aS += 1.0f;
        }
    }
    if (cur >= 0 && (aL != 0.0f || aS != 0.0f)) {
        atomicAdd(&g_lpg[cur], aL);
        atomicAdd(&g_selsum[cur], aS);
    }
}
__global__ void k_fin(float* __restrict__ out) {
    int g = threadIdx.x;
    __shared__ float rs[32], rc[32];
    __shared__ float s_res;
    float lpg = g_lpg[g];
    float has = (g_selsum[g] > 0.0f) ? 1.0f : 0.0f;
    float v1 = -lpg * has, v2 = has;
    #pragma unroll
    for (int o = 16; o; o >>= 1) {
        v1 += __shfl_xor_sync(0xffffffffu, v1, o);
        v2 += __shfl_xor_sync(0xffffffffu, v2, o);
    }
    if ((g & 31) == 0) { rs[g >> 5] = v1; rc[g >> 5] = v2; }
    __syncthreads();
    if (g < 32) {
        float a = rs[g], b = rc[g];
        #pragma unroll
        for (int o = 16; o; o >>= 1) {
            a += __shfl_xor_sync(0xffffffffu, a, o);
            b += __shfl_xor_sync(0xffffffffu, b, o);
        }
        if (g == 0) s_res = a / fmaxf(b, 1.0f);
    }
    __syncthreads();
    out[g * 3 + 1] = lpg;
    out[g * 3 + 2] = s_res;
}

// ---------------- host ----------------
extern "C" void kernel_launch(void* const* d_in, const int* in_sizes, int n_in,
                              void* d_out, int out_size) {
    int I_node, I_q, I_edge, I_loc, I_ptr, I_eb, I_mask, I_eidx;
    int I_ln1g, I_ln1b, I_zw1, I_zb1, I_zw2, I_zb2;
    int I_cw1, I_cb1, I_cw2, I_cb2, I_blng, I_blnb, I_bw1, I_bb1, I_bw2, I_bb2;
    if (in_sizes[3] == 4096) {  // dict order
        I_node = 0; I_q = 1; I_edge = 2; I_loc = 3; I_ptr = 4; I_eb = 5; I_mask = 6; I_eidx = 7;
        I_ln1g = 8; I_ln1b = 9; I_zw1 = 10; I_zb1 = 11; I_zw2 = 12; I_zb2 = 13;
        I_cw1 = 14; I_cb1 = 15; I_cw2 = 16; I_cb2 = 17;
        I_blng = 18; I_blnb = 19; I_bw1 = 20; I_bb1 = 21; I_bw2 = 22; I_bb2 = 23;
    } else {                    // signature order
        I_node = 0; I_q = 1; I_edge = 2;
        I_ln1g = 3; I_ln1b = 4; I_zw1 = 5; I_zb1 = 6; I_zw2 = 7; I_zb2 = 8;
        I_cw1 = 9; I_cb1 = 10; I_cw2 = 11; I_cb2 = 12;
        I_blng = 13; I_blnb = 14; I_bw1 = 15; I_bb1 = 16; I_bw2 = 17; I_bb2 = 18;
        I_loc = 19; I_ptr = 20; I_eb = 21; I_mask = 22; I_eidx = 23;
    }

    const float* nodes = (const float*)d_in[I_node];
    const float* qt    = (const float*)d_in[I_q];
    const float* et    = (const float*)d_in[I_edge];
    const int*   locs  = (const int*)d_in[I_loc];
    const int*   ptr   = (const int*)d_in[I_ptr];
    const int*   ebat  = (const int*)d_in[I_eb];
    const int*   mask  = (const int*)d_in[I_mask];
    const int*   eidx  = (const int*)d_in[I_eidx];
    float* out = (float*)d_out;

    int dev = 0, nsm = 148;
    cudaGetDevice(&dev);
    cudaDeviceGetAttribute(&nsm, cudaDevAttrMultiProcessorCount, dev);

    static int smem_set = 0;
    static cudaStream_t s2 = 0, s3 = 0;
    static cudaEvent_t ev_fork = 0, ev_join = 0, ev_cvt = 0;
    if (!smem_set) {
        cudaFuncSetAttribute(k_edge, cudaFuncAttributeMaxDynamicSharedMemorySize, SM_TOTAL);
        cudaStreamCreateWithFlags(&s2, cudaStreamNonBlocking);
        cudaStreamCreateWithFlags(&s3, cudaStreamNonBlocking);
        cudaEventCreateWithFlags(&ev_fork, cudaEventDisableTiming);
        cudaEventCreateWithFlags(&ev_join, cudaEventDisableTiming);
        cudaEventCreateWithFlags(&ev_cvt, cudaEventDisableTiming);
        smem_set = 1;
    }

    uint2* p_nbf; uint2* p_qbf;
    float2* p_nst; float2* p_qst;
    float* p_exp;
    cudaGetSymbolAddress((void**)&p_nbf, g_nbf);
    cudaGetSymbolAddress((void**)&p_qbf, g_qbf);
    cudaGetSymbolAddress((void**)&p_nst, g_nstat);
    cudaGetSymbolAddress((void**)&p_qst, g_qstat);
    cudaGetSymbolAddress((void**)&p_exp, g_expsum);

    // fork point
    cudaEventRecord(ev_fork, 0);
    cudaStreamWaitEvent(s2, ev_fork, 0);
    cudaStreamWaitEvent(s3, ev_fork, 0);

    // s2: fused start-attention + ctx MLP + log_z (independent of k_edge chain)
    k_sctx<<<Gn, 128, 0, s2>>>(nodes, qt, locs, ptr,
                        (const float*)d_in[I_cw1], (const float*)d_in[I_cb1],
                        (const float*)d_in[I_cw2], (const float*)d_in[I_cb2],
                        (const float*)d_in[I_ln1g], (const float*)d_in[I_ln1b],
                        (const float*)d_in[I_zw1], (const float*)d_in[I_zb1],
                        (const float*)d_in[I_zw2], (const float*)d_in[I_zb2],
                        out);
    cudaEventRecord(ev_join, s2);

    // s3: token conversions (cvt-nodes also zeroes g_expsum)
    k_cvt<<<(NNODES + 7) / 8, 256, 0, s3>>>((const float4*)nodes, p_nbf, p_nst, p_exp, NNODES);
    k_cvt<<<(Gn + 7) / 8, 256, 0, s3>>>((const float4*)qt, p_qbf, p_qst, nullptr, Gn);
    cudaEventRecord(ev_cvt, s3);

    // main chain: init + prep run concurrently with s3 cvt
    k_init<<<(Gn + 255) / 256, 256>>>();
    k_prep<<<128, 384>>>((const float*)d_in[I_bw1], (const float*)d_in[I_blng],
                         (const float*)d_in[I_blnb], (const float*)d_in[I_bb1]);
    cudaStreamWaitEvent(0, ev_cvt, 0);
    k_edge<<<nsm, 512, SM_TOTAL>>>(et, ebat, eidx,
                                   (const float*)d_in[I_bw2], (const float*)d_in[I_bb2]);
    k_lpb<<<((NEDGES + 15) / 16 + 255) / 256, 256>>>(eidx, ebat, mask);
    cudaStreamWaitEvent(0, ev_join, 0);
    k_fin<<<1, 1024>>>(out);
}